// round 6
// baseline (speedup 1.0000x reference)
#include <cuda_runtime.h>
#include <cuda_bf16.h>
#include <cstdint>
#include <cstddef>

// Problem constants (fixed by setup_inputs: BS=8, L=2048, D=2048, CACHE=64)
#define BSQ   8
#define LSEQ  2048
#define TOK   16384          // BS*L
#define ROWS  16392          // TOK + BS (padded buffer rows)
#define DDIM  2048
#define H1    1024           // conv1 output width
#define N2    4096           // conv2 GEMM output width (2*D)

// ---------------------------------------------------------------------------
// Device-global scratch (allocation-free path)
// ---------------------------------------------------------------------------
__device__ __nv_bfloat16 g_XT1h[(size_t)ROWS * DDIM];
__device__ __nv_bfloat16 g_XT1l[(size_t)ROWS * DDIM];
__device__ __nv_bfloat16 g_XT2h[(size_t)ROWS * H1];
__device__ __nv_bfloat16 g_XT2l[(size_t)ROWS * H1];
__device__ __nv_bfloat16 g_W1th[(size_t)DDIM * DDIM];   // W1^T hi  [N][K]
__device__ __nv_bfloat16 g_W1tl[(size_t)DDIM * DDIM];
__device__ __nv_bfloat16 g_W2th[(size_t)N2 * H1];       // W2^T hi
__device__ __nv_bfloat16 g_W2tl[(size_t)N2 * H1];
__device__ float g_C1[(size_t)ROWS * DDIM];
__device__ float g_C2[(size_t)ROWS * N2];

// ---------------------------------------------------------------------------
// helpers
// ---------------------------------------------------------------------------
__device__ __forceinline__ uint32_t smem_u32(const void* p) {
    uint32_t a;
    asm("{ .reg .u64 t; cvta.to.shared.u64 t, %1; cvt.u32.u64 %0, t; }"
        : "=r"(a) : "l"(p));
    return a;
}
__device__ __forceinline__ void cp_async16(uint32_t dst, const void* src, uint32_t bytes) {
    asm volatile("cp.async.cg.shared.global [%0], [%1], 16, %2;"
                 :: "r"(dst), "l"(src), "r"(bytes) : "memory");
}
__device__ __forceinline__ void ldsm_x4(uint32_t& r0, uint32_t& r1,
                                        uint32_t& r2, uint32_t& r3, uint32_t addr) {
    asm volatile("ldmatrix.sync.aligned.m8n8.x4.shared.b16 {%0,%1,%2,%3}, [%4];"
                 : "=r"(r0), "=r"(r1), "=r"(r2), "=r"(r3) : "r"(addr));
}
__device__ __forceinline__ void mma_bf16(float& c0, float& c1, float& c2, float& c3,
                                         uint32_t a0, uint32_t a1, uint32_t a2, uint32_t a3,
                                         uint32_t b0, uint32_t b1) {
    asm volatile(
        "mma.sync.aligned.m16n8k16.row.col.f32.bf16.bf16.f32 "
        "{%0,%1,%2,%3}, {%4,%5,%6,%7}, {%8,%9}, {%0,%1,%2,%3};"
        : "+f"(c0), "+f"(c1), "+f"(c2), "+f"(c3)
        : "r"(a0), "r"(a1), "r"(a2), "r"(a3), "r"(b0), "r"(b1));
}

// ---------------------------------------------------------------------------
// bf16 mma.sync GEMM: C[M,N] = A[M,K] * Bt[N,K]^T, 3-way bf16 split fused as
// 3 K-phases: (Ahi,Bhi), (Alo,Bhi), (Ahi,Blo) into the same accumulators.
// Block tile 128x256x64, 8 warps (2x4), warp tile 64x64, 3-stage cp.async,
// ldmatrix fragment loads (144B row pitch -> conflict-free LDSM),
// ONE __syncthreads per mainloop iteration.
// ---------------------------------------------------------------------------
#define GS 3
#define PITCH 144
#define ATILE_B (128 * PITCH)          // 18432
#define BTILE_B (256 * PITCH)          // 36864
#define STAGE_B (ATILE_B + BTILE_B)    // 55296
#define GSMEM_TOTAL (GS * STAGE_B)     // 165888

__global__ __launch_bounds__(256, 1)
void mma_gemm_kernel(const __nv_bfloat16* __restrict__ Ahi,
                     const __nv_bfloat16* __restrict__ Alo,
                     const __nv_bfloat16* __restrict__ Bhi,
                     const __nv_bfloat16* __restrict__ Blo,
                     float* __restrict__ C, int M, int K, int N)
{
    extern __shared__ char smem[];
    const uint32_t sbase = smem_u32(smem);
    const int tid  = threadIdx.x;
    const int wid  = tid >> 5;
    const int lane = tid & 31;
    const int wm   = wid & 1;          // 0..1 (64 rows each)
    const int wn   = wid >> 1;         // 0..3 (64 cols each)
    const int g    = lane >> 2;        // 0..7
    const int tig  = lane & 3;         // 0..3

    const int nbase = blockIdx.x * 256;
    const int mbase = blockIdx.y * 128;

    const int NK  = K >> 6;            // K tiles of 64
    const int TOT = 3 * NK;

    const __nv_bfloat16* Aph[3] = {Ahi, Alo, Ahi};
    const __nv_bfloat16* Bph[3] = {Bhi, Bhi, Blo};

    // ldmatrix per-lane base offsets (within a stage's A / B region)
    const uint32_t aoff = (uint32_t)(wm * 64 + (lane & 7) + ((lane >> 3) & 1) * 8) * PITCH
                        + (uint32_t)(lane >> 4) * 16;
    const uint32_t boff = (uint32_t)(wn * 64 + ((lane >> 4) & 1) * 8 + (lane & 7)) * PITCH
                        + (uint32_t)((lane >> 3) & 1) * 16;

    // producer: A 128x128B = 1024 chunks, B 256x128B = 2048 chunks (16B each)
    auto produce = [&](int pi) {
        const int st = pi % GS;
        const int ph = pi / NK;
        const int kk = (pi - ph * NK) << 6;
        const __nv_bfloat16* Ap = Aph[ph];
        const __nv_bfloat16* Bp = Bph[ph];
        const uint32_t sA = sbase + st * STAGE_B;
        const uint32_t sB = sA + ATILE_B;
        #pragma unroll
        for (int h = 0; h < 4; h++) {
            int c  = tid + h * 256;
            int r  = c >> 3;
            int cc = c & 7;
            int grow = mbase + r;
            uint32_t ok = (grow < M) ? 16u : 0u;
            const void* srcA = Ap + ((size_t)(ok ? grow : 0) * K + kk + cc * 8);
            cp_async16(sA + r * PITCH + cc * 16, srcA, ok);
        }
        #pragma unroll
        for (int h = 0; h < 8; h++) {
            int c  = tid + h * 256;
            int r  = c >> 3;
            int cc = c & 7;
            const void* srcB = Bp + ((size_t)(nbase + r) * K + kk + cc * 8);
            cp_async16(sB + r * PITCH + cc * 16, srcB, 16u);
        }
        asm volatile("cp.async.commit_group;" ::: "memory");
    };

    float acc[4][8][4];
    #pragma unroll
    for (int mt = 0; mt < 4; mt++)
        #pragma unroll
        for (int nt = 0; nt < 8; nt++)
            #pragma unroll
            for (int e = 0; e < 4; e++)
                acc[mt][nt][e] = 0.f;

    // prologue: prefetch GS-1 stages
    produce(0); produce(1);

    for (int it = 0; it < TOT; it++) {
        asm volatile("cp.async.wait_group 1;" ::: "memory");
        __syncthreads();
        if (it + 2 < TOT) produce(it + 2);

        const int st = it % GS;
        const uint32_t sA = sbase + st * STAGE_B;
        const uint32_t sB = sA + ATILE_B;

        #pragma unroll
        for (int kk = 0; kk < 64; kk += 16) {
            uint32_t af[4][4];
            #pragma unroll
            for (int mt = 0; mt < 4; mt++)
                ldsm_x4(af[mt][0], af[mt][1], af[mt][2], af[mt][3],
                        sA + aoff + (uint32_t)mt * (16 * PITCH) + (uint32_t)kk * 2);
            #pragma unroll
            for (int np = 0; np < 4; np++) {
                uint32_t b0, b1, b2, b3;
                ldsm_x4(b0, b1, b2, b3,
                        sB + boff + (uint32_t)np * (16 * PITCH) + (uint32_t)kk * 2);
                #pragma unroll
                for (int mt = 0; mt < 4; mt++) {
                    mma_bf16(acc[mt][2 * np][0], acc[mt][2 * np][1],
                             acc[mt][2 * np][2], acc[mt][2 * np][3],
                             af[mt][0], af[mt][1], af[mt][2], af[mt][3], b0, b1);
                    mma_bf16(acc[mt][2 * np + 1][0], acc[mt][2 * np + 1][1],
                             acc[mt][2 * np + 1][2], acc[mt][2 * np + 1][3],
                             af[mt][0], af[mt][1], af[mt][2], af[mt][3], b2, b3);
                }
            }
        }
    }

    // store
    #pragma unroll
    for (int mt = 0; mt < 4; mt++) {
        int row = mbase + wm * 64 + mt * 16 + g;
        #pragma unroll
        for (int nt = 0; nt < 8; nt++) {
            int col = nbase + wn * 64 + nt * 8 + tig * 2;
            if (row < M) {
                float2 v = make_float2(acc[mt][nt][0], acc[mt][nt][1]);
                *(float2*)(C + (size_t)row * N + col) = v;
            }
            if (row + 8 < M) {
                float2 v = make_float2(acc[mt][nt][2], acc[mt][nt][3]);
                *(float2*)(C + (size_t)(row + 8) * N + col) = v;
            }
        }
    }
}

// ---------------------------------------------------------------------------
// E0: build XT1 hi/lo from inputs/lf1 (p = s*2049+j; j==0 -> cache row)
// ---------------------------------------------------------------------------
__global__ void build_xt1_kernel(const float* __restrict__ inputs,
                                 const float* __restrict__ lf1)
{
    int p = blockIdx.x;
    int s = p / (LSEQ + 1);
    int j = p - s * (LSEQ + 1);
    const float* src = (j == 0)
        ? (lf1 + (size_t)s * DDIM)
        : (inputs + ((size_t)s * LSEQ + (j - 1)) * DDIM);
    __nv_bfloat16* dh = g_XT1h + (size_t)p * DDIM;
    __nv_bfloat16* dl = g_XT1l + (size_t)p * DDIM;
    int base = threadIdx.x * 8;
    #pragma unroll
    for (int v = 0; v < 2; v++) {
        float4 x = *(const float4*)(src + base + v * 4);
        float xs[4] = {x.x, x.y, x.z, x.w};
        #pragma unroll
        for (int e = 0; e < 4; e++) {
            __nv_bfloat16 h = __float2bfloat16_rn(xs[e]);
            dh[base + v * 4 + e] = h;
            dl[base + v * 4 + e] = __float2bfloat16_rn(xs[e] - __bfloat162float(h));
        }
    }
}

// ---------------------------------------------------------------------------
// E1: XT2[p] hi/lo = split( j==0 ? lf2[s] : C1[p-1,:1024] + C1[p,1024:] + b1 )
// ---------------------------------------------------------------------------
__global__ void build_xt2_kernel(const float* __restrict__ lf2,
                                 const float* __restrict__ b1)
{
    int p = blockIdx.x;
    int s = p / (LSEQ + 1);
    int j = p - s * (LSEQ + 1);
    __nv_bfloat16* dh = g_XT2h + (size_t)p * H1;
    __nv_bfloat16* dl = g_XT2l + (size_t)p * H1;
    int base = threadIdx.x * 4;
    float4 r;
    if (j == 0) {
        r = *(const float4*)(lf2 + (size_t)s * H1 + base);
    } else {
        float4 a = *(const float4*)(g_C1 + (size_t)(p - 1) * DDIM + base);
        float4 b = *(const float4*)(g_C1 + (size_t)p * DDIM + H1 + base);
        float4 c = *(const float4*)(b1 + base);
        r.x = a.x + b.x + c.x;  r.y = a.y + b.y + c.y;
        r.z = a.z + b.z + c.z;  r.w = a.w + b.w + c.w;
    }
    float xs[4] = {r.x, r.y, r.z, r.w};
    #pragma unroll
    for (int e = 0; e < 4; e++) {
        __nv_bfloat16 h = __float2bfloat16_rn(xs[e]);
        dh[base + e] = h;
        dl[base + e] = __float2bfloat16_rn(xs[e] - __bfloat162float(h));
    }
}

// ---------------------------------------------------------------------------
// Transpose + split: out[c][r] = split(W[r][c]);  W is [R, Cc], out [Cc, R]
// ---------------------------------------------------------------------------
__global__ void transpose_split_kernel(const float* __restrict__ W, int R, int Cc,
                                       __nv_bfloat16* __restrict__ oh,
                                       __nv_bfloat16* __restrict__ ol)
{
    __shared__ float t[32][33];
    int tx = threadIdx.x, ty = threadIdx.y;           // 32 x 8
    int r0 = blockIdx.y * 32, c0 = blockIdx.x * 32;
    #pragma unroll
    for (int k = 0; k < 4; k++)
        t[ty + 8 * k][tx] = W[(size_t)(r0 + ty + 8 * k) * Cc + c0 + tx];
    __syncthreads();
    #pragma unroll
    for (int k = 0; k < 4; k++) {
        int c = c0 + ty + 8 * k;
        int r = r0 + tx;
        float v = t[tx][ty + 8 * k];
        __nv_bfloat16 h = __float2bfloat16_rn(v);
        oh[(size_t)c * R + r] = h;
        ol[(size_t)c * R + r] = __float2bfloat16_rn(v - __bfloat162float(h));
    }
}

// ---------------------------------------------------------------------------
// E2: epilogue (shift-add + bias + residual + RMSNorm)
// ---------------------------------------------------------------------------
__global__ void epilogue_kernel(const float* __restrict__ inputs,
                                const float* __restrict__ b2,
                                const float* __restrict__ lnw,
                                float* __restrict__ out)
{
    int t = blockIdx.x;
    int s = t >> 11;
    int j = t & 2047;
    size_t p = (size_t)s * (LSEQ + 1) + j;

    const float* rowA = g_C2 + p * N2;
    const float* rowB = g_C2 + (p + 1) * N2 + DDIM;
    const float* xin  = inputs + (size_t)t * DDIM;

    int base = threadIdx.x * 8;
    float o[8];
    float ss = 0.f;
    #pragma unroll
    for (int v = 0; v < 2; v++) {
        float4 a  = *(const float4*)(rowA + base + v * 4);
        float4 b  = *(const float4*)(rowB + base + v * 4);
        float4 bi = *(const float4*)(b2   + base + v * 4);
        float4 xi = *(const float4*)(xin  + base + v * 4);
        float r0 = a.x + b.x + bi.x + xi.x;
        float r1 = a.y + b.y + bi.y + xi.y;
        float r2 = a.z + b.z + bi.z + xi.z;
        float r3 = a.w + b.w + bi.w + xi.w;
        o[v * 4 + 0] = r0; o[v * 4 + 1] = r1; o[v * 4 + 2] = r2; o[v * 4 + 3] = r3;
        ss += r0 * r0 + r1 * r1 + r2 * r2 + r3 * r3;
    }

    __shared__ float red[8];
    #pragma unroll
    for (int off = 16; off > 0; off >>= 1)
        ss += __shfl_xor_sync(0xFFFFFFFFu, ss, off);
    int lane = threadIdx.x & 31;
    int wid  = threadIdx.x >> 5;
    if (lane == 0) red[wid] = ss;
    __syncthreads();
    float total = 0.f;
    #pragma unroll
    for (int w = 0; w < 8; w++) total += red[w];

    float scale = rsqrtf(total * (1.0f / DDIM) + 1e-6f);

    float* op = out + (size_t)t * DDIM;
    #pragma unroll
    for (int v = 0; v < 2; v++) {
        float4 lw = *(const float4*)(lnw + base + v * 4);
        float4 r;
        r.x = o[v * 4 + 0] * scale * lw.x;
        r.y = o[v * 4 + 1] * scale * lw.y;
        r.z = o[v * 4 + 2] * scale * lw.z;
        r.w = o[v * 4 + 3] * scale * lw.w;
        *(float4*)(op + base + v * 4) = r;
    }
}

// ---------------------------------------------------------------------------
// kernel_launch
// ---------------------------------------------------------------------------
extern "C" void kernel_launch(void* const* d_in, const int* in_sizes, int n_in,
                              void* d_out, int out_size)
{
    const float* inputs = (const float*)d_in[0];
    const float* lf1    = (const float*)d_in[7];
    const float* lf2    = (const float*)d_in[8];
    const float* W1     = (const float*)d_in[9];
    const float* W2     = (const float*)d_in[10];
    const float* b1     = (const float*)d_in[11];
    const float* b2     = (const float*)d_in[12];
    const float* lnw    = (const float*)d_in[13];
    float* out          = (float*)d_out;

    static __nv_bfloat16 *pXT1h, *pXT1l, *pXT2h, *pXT2l, *pW1h, *pW1l, *pW2h, *pW2l;
    static float *pC1, *pC2;
    static bool init_done = false;
    if (!init_done) {
        cudaGetSymbolAddress((void**)&pXT1h, g_XT1h);
        cudaGetSymbolAddress((void**)&pXT1l, g_XT1l);
        cudaGetSymbolAddress((void**)&pXT2h, g_XT2h);
        cudaGetSymbolAddress((void**)&pXT2l, g_XT2l);
        cudaGetSymbolAddress((void**)&pW1h,  g_W1th);
        cudaGetSymbolAddress((void**)&pW1l,  g_W1tl);
        cudaGetSymbolAddress((void**)&pW2h,  g_W2th);
        cudaGetSymbolAddress((void**)&pW2l,  g_W2tl);
        cudaGetSymbolAddress((void**)&pC1,   g_C1);
        cudaGetSymbolAddress((void**)&pC2,   g_C2);
        cudaFuncSetAttribute(mma_gemm_kernel,
                             cudaFuncAttributeMaxDynamicSharedMemorySize, GSMEM_TOTAL);
        init_done = true;
    }

    // E0: split inputs+cache into XT1 hi/lo
    build_xt1_kernel<<<ROWS, 256>>>(inputs, lf1);

    // Weight transposes + splits
    transpose_split_kernel<<<dim3(DDIM / 32, DDIM / 32), dim3(32, 8)>>>(W1, DDIM, DDIM, pW1h, pW1l);
    transpose_split_kernel<<<dim3(N2 / 32, H1 / 32),   dim3(32, 8)>>>(W2, H1, N2, pW2h, pW2l);

    // G1: C1 = XT1 @ W1   [16392,2048]x[2048,2048]
    {
        dim3 grid(DDIM / 256, (ROWS + 127) / 128);   // 8 x 129
        mma_gemm_kernel<<<grid, 256, GSMEM_TOTAL>>>(pXT1h, pXT1l, pW1h, pW1l,
                                                    pC1, ROWS, DDIM, DDIM);
    }

    // E1: build XT2 hi/lo from C1
    build_xt2_kernel<<<ROWS, 256>>>(lf2, b1);

    // G2: C2 = XT2 @ W2   [16392,1024]x[1024,4096]
    {
        dim3 grid(N2 / 256, (ROWS + 127) / 128);     // 16 x 129
        mma_gemm_kernel<<<grid, 256, GSMEM_TOTAL>>>(pXT2h, pXT2l, pW2h, pW2l,
                                                    pC2, ROWS, H1, N2);
    }

    // E2: epilogue
    epilogue_kernel<<<TOK, 256>>>(inputs, b2, lnw, out);
}

// round 9
// speedup vs baseline: 1.1387x; 1.1387x over previous
#include <cuda_runtime.h>
#include <cuda_bf16.h>
#include <cstdint>
#include <cstddef>

// Problem constants (fixed by setup_inputs: BS=8, L=2048, D=2048, CACHE=64)
#define BSQ   8
#define LSEQ  2048
#define TOK   16384          // BS*L
#define ROWS  16392          // TOK + BS (padded buffer rows)
#define DDIM  2048
#define H1    1024           // conv1 output width
#define K2    2048           // GEMM2 K after Z-concat
#define N2P   2048           // GEMM2 N after fold

// ---------------------------------------------------------------------------
// Device-global scratch (allocation-free path)
// ---------------------------------------------------------------------------
__device__ __nv_bfloat16 g_XT1h[(size_t)ROWS * DDIM];
__device__ __nv_bfloat16 g_XT1l[(size_t)ROWS * DDIM];
__device__ __nv_bfloat16 g_Zh[(size_t)TOK * K2];        // Z = [XT2[p], XT2[p+1]]
__device__ __nv_bfloat16 g_Zl[(size_t)TOK * K2];
__device__ __nv_bfloat16 g_W1th[(size_t)DDIM * DDIM];   // W1^T hi  [N][K]
__device__ __nv_bfloat16 g_W1tl[(size_t)DDIM * DDIM];
__device__ __nv_bfloat16 g_W2ph[(size_t)N2P * K2];      // W2' ^T hi [N][K]
__device__ __nv_bfloat16 g_W2pl[(size_t)N2P * K2];
__device__ float g_C1[(size_t)ROWS * DDIM];
__device__ float g_C2[(size_t)TOK * N2P];

// ---------------------------------------------------------------------------
// helpers
// ---------------------------------------------------------------------------
__device__ __forceinline__ uint32_t smem_u32(const void* p) {
    uint32_t a;
    asm("{ .reg .u64 t; cvta.to.shared.u64 t, %1; cvt.u32.u64 %0, t; }"
        : "=r"(a) : "l"(p));
    return a;
}
__device__ __forceinline__ void cp_async16(uint32_t dst, const void* src, uint32_t bytes) {
    asm volatile("cp.async.cg.shared.global [%0], [%1], 16, %2;"
                 :: "r"(dst), "l"(src), "r"(bytes) : "memory");
}
__device__ __forceinline__ void ldsm_x4(uint32_t& r0, uint32_t& r1,
                                        uint32_t& r2, uint32_t& r3, uint32_t addr) {
    asm volatile("ldmatrix.sync.aligned.m8n8.x4.shared.b16 {%0,%1,%2,%3}, [%4];"
                 : "=r"(r0), "=r"(r1), "=r"(r2), "=r"(r3) : "r"(addr));
}
__device__ __forceinline__ void mma_bf16(float& c0, float& c1, float& c2, float& c3,
                                         uint32_t a0, uint32_t a1, uint32_t a2, uint32_t a3,
                                         uint32_t b0, uint32_t b1) {
    asm volatile(
        "mma.sync.aligned.m16n8k16.row.col.f32.bf16.bf16.f32 "
        "{%0,%1,%2,%3}, {%4,%5,%6,%7}, {%8,%9}, {%0,%1,%2,%3};"
        : "+f"(c0), "+f"(c1), "+f"(c2), "+f"(c3)
        : "r"(a0), "r"(a1), "r"(a2), "r"(a3), "r"(b0), "r"(b1));
}

// ---------------------------------------------------------------------------
// bf16 mma.sync GEMM: C[M,N] = A[M,K] * Bt[N,K]^T, 3-way bf16 split fused as
// 3 K-phases: (Ahi,Bhi), (Alo,Bhi), (Ahi,Blo) into the same accumulators.
// Block tile 128x128x64, 8 warps (2x4), warp tile 64x32, 3-stage cp.async,
// ldmatrix fragment loads (144B pitch -> conflict-free), ONE sync per iter,
// producer issued after the first kk-chunk so MMAs start right post-barrier.
// ---------------------------------------------------------------------------
#define GS 3
#define PITCH 144
#define ATILE_B (128 * PITCH)          // 18432
#define STAGE_B (2 * ATILE_B)          // 36864
#define GSMEM_TOTAL (GS * STAGE_B)     // 110592

__global__ __launch_bounds__(256, 2)
void mma_gemm_kernel(const __nv_bfloat16* __restrict__ Ahi,
                     const __nv_bfloat16* __restrict__ Alo,
                     const __nv_bfloat16* __restrict__ Bhi,
                     const __nv_bfloat16* __restrict__ Blo,
                     float* __restrict__ C, int M, int K, int N)
{
    extern __shared__ char smem[];
    const uint32_t sbase = smem_u32(smem);
    const int tid  = threadIdx.x;
    const int wid  = tid >> 5;
    const int lane = tid & 31;
    const int wm   = wid & 1;          // 0..1
    const int wn   = wid >> 1;         // 0..3
    const int g    = lane >> 2;        // 0..7
    const int tig  = lane & 3;         // 0..3

    const int nbase = blockIdx.x * 128;
    const int mbase = blockIdx.y * 128;

    const int NK  = K >> 6;            // K tiles of 64
    const int TOT = 3 * NK;

    const __nv_bfloat16* Aph[3] = {Ahi, Alo, Ahi};
    const __nv_bfloat16* Bph[3] = {Bhi, Bhi, Blo};

    // ldmatrix per-lane base offsets (within a stage's A / B region)
    const uint32_t aoff = (uint32_t)(wm * 64 + (lane & 7) + ((lane >> 3) & 1) * 8) * PITCH
                        + (uint32_t)(lane >> 4) * 16;
    const uint32_t boff = (uint32_t)(wn * 32 + ((lane >> 4) & 1) * 8 + (lane & 7)) * PITCH
                        + (uint32_t)((lane >> 3) & 1) * 16;

    auto produce = [&](int pi) {
        const int st = pi % GS;
        const int ph = pi / NK;
        const int kk = (pi - ph * NK) << 6;
        const __nv_bfloat16* Ap = Aph[ph];
        const __nv_bfloat16* Bp = Bph[ph];
        const uint32_t sA = sbase + st * STAGE_B;
        const uint32_t sB = sA + ATILE_B;
        #pragma unroll
        for (int h = 0; h < 4; h++) {
            int c  = tid + h * 256;
            int r  = c >> 3;
            int cc = c & 7;
            int grow = mbase + r;
            uint32_t ok = (grow < M) ? 16u : 0u;
            const void* srcA = Ap + ((size_t)(ok ? grow : 0) * K + kk + cc * 8);
            cp_async16(sA + r * PITCH + cc * 16, srcA, ok);
            const void* srcB = Bp + ((size_t)(nbase + r) * K + kk + cc * 8);
            cp_async16(sB + r * PITCH + cc * 16, srcB, 16u);
        }
        asm volatile("cp.async.commit_group;" ::: "memory");
    };

    float acc[4][4][4];
    #pragma unroll
    for (int mt = 0; mt < 4; mt++)
        #pragma unroll
        for (int nt = 0; nt < 4; nt++)
            #pragma unroll
            for (int e = 0; e < 4; e++)
                acc[mt][nt][e] = 0.f;

    // prologue: prefetch GS-1 stages
    produce(0); produce(1);

    for (int it = 0; it < TOT; it++) {
        asm volatile("cp.async.wait_group 1;" ::: "memory");
        __syncthreads();

        const int st = it % GS;
        const uint32_t sA = sbase + st * STAGE_B;
        const uint32_t sB = sA + ATILE_B;

        auto do_chunk = [&](int kk) {
            uint32_t bf[4][2];
            #pragma unroll
            for (int np = 0; np < 2; np++) {
                ldsm_x4(bf[2 * np][0], bf[2 * np][1],
                        bf[2 * np + 1][0], bf[2 * np + 1][1],
                        sB + boff + (uint32_t)np * (16 * PITCH) + (uint32_t)kk * 2);
            }
            #pragma unroll
            for (int mt = 0; mt < 4; mt++) {
                uint32_t a0, a1, a2, a3;
                ldsm_x4(a0, a1, a2, a3,
                        sA + aoff + (uint32_t)mt * (16 * PITCH) + (uint32_t)kk * 2);
                #pragma unroll
                for (int nt = 0; nt < 4; nt++)
                    mma_bf16(acc[mt][nt][0], acc[mt][nt][1],
                             acc[mt][nt][2], acc[mt][nt][3],
                             a0, a1, a2, a3, bf[nt][0], bf[nt][1]);
            }
        };

        do_chunk(0);
        if (it + 2 < TOT) produce(it + 2);   // writes stage (it+2)%3 != it%3
        do_chunk(16);
        do_chunk(32);
        do_chunk(48);
    }

    // store
    #pragma unroll
    for (int mt = 0; mt < 4; mt++) {
        int row = mbase + wm * 64 + mt * 16 + g;
        #pragma unroll
        for (int nt = 0; nt < 4; nt++) {
            int col = nbase + wn * 32 + nt * 8 + tig * 2;
            if (row < M) {
                float2 v = make_float2(acc[mt][nt][0], acc[mt][nt][1]);
                *(float2*)(C + (size_t)row * N + col) = v;
            }
            if (row + 8 < M) {
                float2 v = make_float2(acc[mt][nt][2], acc[mt][nt][3]);
                *(float2*)(C + (size_t)(row + 8) * N + col) = v;
            }
        }
    }
}

// ---------------------------------------------------------------------------
// E0: build XT1 hi/lo from inputs/lf1 (p = s*2049+j; j==0 -> cache row)
// ---------------------------------------------------------------------------
__global__ void build_xt1_kernel(const float* __restrict__ inputs,
                                 const float* __restrict__ lf1)
{
    int p = blockIdx.x;
    int s = p / (LSEQ + 1);
    int j = p - s * (LSEQ + 1);
    const float* src = (j == 0)
        ? (lf1 + (size_t)s * DDIM)
        : (inputs + ((size_t)s * LSEQ + (j - 1)) * DDIM);
    __nv_bfloat16* dh = g_XT1h + (size_t)p * DDIM;
    __nv_bfloat16* dl = g_XT1l + (size_t)p * DDIM;
    int base = threadIdx.x * 8;
    #pragma unroll
    for (int v = 0; v < 2; v++) {
        float4 x = *(const float4*)(src + base + v * 4);
        float xs[4] = {x.x, x.y, x.z, x.w};
        #pragma unroll
        for (int e = 0; e < 4; e++) {
            __nv_bfloat16 h = __float2bfloat16_rn(xs[e]);
            dh[base + v * 4 + e] = h;
            dl[base + v * 4 + e] = __float2bfloat16_rn(xs[e] - __bfloat162float(h));
        }
    }
}

// ---------------------------------------------------------------------------
// E1: build Z[t] = [ XT2[p] , XT2[p+1] ]  (p = s*2049 + j for token t=(s,j))
//   XT2[q] = (q at j==0) ? lf2[s] : C1[q-1,:1024] + C1[q,1024:] + b1
// one block per token, 256 threads: 4 cols per half per thread
// ---------------------------------------------------------------------------
__global__ void build_z_kernel(const float* __restrict__ lf2,
                               const float* __restrict__ b1)
{
    int t = blockIdx.x;
    int s = t >> 11;
    int j = t & 2047;
    size_t p = (size_t)s * (LSEQ + 1) + j;

    __nv_bfloat16* zh = g_Zh + (size_t)t * K2;
    __nv_bfloat16* zl = g_Zl + (size_t)t * K2;
    int base = threadIdx.x * 4;
    float4 bi = *(const float4*)(b1 + base);

    // half 1: XT2[p]
    float4 r1;
    if (j == 0) {
        r1 = *(const float4*)(lf2 + (size_t)s * H1 + base);
    } else {
        float4 a = *(const float4*)(g_C1 + (p - 1) * DDIM + base);
        float4 b = *(const float4*)(g_C1 + p * DDIM + H1 + base);
        r1.x = a.x + b.x + bi.x;  r1.y = a.y + b.y + bi.y;
        r1.z = a.z + b.z + bi.z;  r1.w = a.w + b.w + bi.w;
    }
    // half 2: XT2[p+1] (always the conv path; p+1 has j>=1)
    float4 a2 = *(const float4*)(g_C1 + p * DDIM + base);
    float4 b2 = *(const float4*)(g_C1 + (p + 1) * DDIM + H1 + base);
    float4 r2;
    r2.x = a2.x + b2.x + bi.x;  r2.y = a2.y + b2.y + bi.y;
    r2.z = a2.z + b2.z + bi.z;  r2.w = a2.w + b2.w + bi.w;

    float h1[4] = {r1.x, r1.y, r1.z, r1.w};
    float h2[4] = {r2.x, r2.y, r2.z, r2.w};
    #pragma unroll
    for (int e = 0; e < 4; e++) {
        __nv_bfloat16 hh = __float2bfloat16_rn(h1[e]);
        zh[base + e] = hh;
        zl[base + e] = __float2bfloat16_rn(h1[e] - __bfloat162float(hh));
        __nv_bfloat16 hh2 = __float2bfloat16_rn(h2[e]);
        zh[H1 + base + e] = hh2;
        zl[H1 + base + e] = __float2bfloat16_rn(h2[e] - __bfloat162float(hh2));
    }
}

// ---------------------------------------------------------------------------
// Transpose + split W1: out[c][r] = split(W[r][c]);  W is [R, Cc], out [Cc, R]
// ---------------------------------------------------------------------------
__global__ void transpose_split_kernel(const float* __restrict__ W, int R, int Cc,
                                       __nv_bfloat16* __restrict__ oh,
                                       __nv_bfloat16* __restrict__ ol)
{
    __shared__ float t[32][33];
    int tx = threadIdx.x, ty = threadIdx.y;           // 32 x 8
    int r0 = blockIdx.y * 32, c0 = blockIdx.x * 32;
    #pragma unroll
    for (int k = 0; k < 4; k++)
        t[ty + 8 * k][tx] = W[(size_t)(r0 + ty + 8 * k) * Cc + c0 + tx];
    __syncthreads();
    #pragma unroll
    for (int k = 0; k < 4; k++) {
        int c = c0 + ty + 8 * k;
        int r = r0 + tx;
        float v = t[tx][ty + 8 * k];
        __nv_bfloat16 h = __float2bfloat16_rn(v);
        oh[(size_t)c * R + r] = h;
        ol[(size_t)c * R + r] = __float2bfloat16_rn(v - __bfloat162float(h));
    }
}

// ---------------------------------------------------------------------------
// Transpose + split W2' : out[n][k'] (2048x2048), where
//   k' < 1024: W2[k'][n] ; k' >= 1024: W2[k'-1024][2048+n]   (W2 is [1024][4096])
// ---------------------------------------------------------------------------
__global__ void transpose_split_w2p_kernel(const float* __restrict__ W2)
{
    __shared__ float t[32][33];
    int tx = threadIdx.x, ty = threadIdx.y;           // 32 x 8
    int k0 = blockIdx.y * 32, n0 = blockIdx.x * 32;
    int half = k0 >> 10;
    int kr0  = k0 & 1023;
    #pragma unroll
    for (int u = 0; u < 4; u++)
        t[ty + 8 * u][tx] = W2[(size_t)(kr0 + ty + 8 * u) * 4096 + half * 2048 + n0 + tx];
    __syncthreads();
    #pragma unroll
    for (int u = 0; u < 4; u++) {
        int n = n0 + ty + 8 * u;
        int k = k0 + tx;
        float v = t[tx][ty + 8 * u];
        __nv_bfloat16 h = __float2bfloat16_rn(v);
        g_W2ph[(size_t)n * K2 + k] = h;
        g_W2pl[(size_t)n * K2 + k] = __float2bfloat16_rn(v - __bfloat162float(h));
    }
}

// ---------------------------------------------------------------------------
// E2: epilogue, now row-local: out[t] = rmsnorm(C2[t] + b2 + inputs[t])
// ---------------------------------------------------------------------------
__global__ void epilogue_kernel(const float* __restrict__ inputs,
                                const float* __restrict__ b2,
                                const float* __restrict__ lnw,
                                float* __restrict__ out)
{
    int t = blockIdx.x;
    const float* rowA = g_C2 + (size_t)t * N2P;
    const float* xin  = inputs + (size_t)t * DDIM;

    int base = threadIdx.x * 8;
    float o[8];
    float ss = 0.f;
    #pragma unroll
    for (int v = 0; v < 2; v++) {
        float4 a  = *(const float4*)(rowA + base + v * 4);
        float4 bi = *(const float4*)(b2   + base + v * 4);
        float4 xi = *(const float4*)(xin  + base + v * 4);
        float r0 = a.x + bi.x + xi.x;
        float r1 = a.y + bi.y + xi.y;
        float r2 = a.z + bi.z + xi.z;
        float r3 = a.w + bi.w + xi.w;
        o[v * 4 + 0] = r0; o[v * 4 + 1] = r1; o[v * 4 + 2] = r2; o[v * 4 + 3] = r3;
        ss += r0 * r0 + r1 * r1 + r2 * r2 + r3 * r3;
    }

    __shared__ float red[8];
    #pragma unroll
    for (int off = 16; off > 0; off >>= 1)
        ss += __shfl_xor_sync(0xFFFFFFFFu, ss, off);
    int lane = threadIdx.x & 31;
    int wid  = threadIdx.x >> 5;
    if (lane == 0) red[wid] = ss;
    __syncthreads();
    float total = 0.f;
    #pragma unroll
    for (int w = 0; w < 8; w++) total += red[w];

    float scale = rsqrtf(total * (1.0f / DDIM) + 1e-6f);

    float* op = out + (size_t)t * DDIM;
    #pragma unroll
    for (int v = 0; v < 2; v++) {
        float4 lw = *(const float4*)(lnw + base + v * 4);
        float4 r;
        r.x = o[v * 4 + 0] * scale * lw.x;
        r.y = o[v * 4 + 1] * scale * lw.y;
        r.z = o[v * 4 + 2] * scale * lw.z;
        r.w = o[v * 4 + 3] * scale * lw.w;
        *(float4*)(op + base + v * 4) = r;
    }
}

// ---------------------------------------------------------------------------
// kernel_launch
// ---------------------------------------------------------------------------
extern "C" void kernel_launch(void* const* d_in, const int* in_sizes, int n_in,
                              void* d_out, int out_size)
{
    const float* inputs = (const float*)d_in[0];
    const float* lf1    = (const float*)d_in[7];
    const float* lf2    = (const float*)d_in[8];
    const float* W1     = (const float*)d_in[9];
    const float* W2     = (const float*)d_in[10];
    const float* b1     = (const float*)d_in[11];
    const float* b2     = (const float*)d_in[12];
    const float* lnw    = (const float*)d_in[13];
    float* out          = (float*)d_out;

    static __nv_bfloat16 *pXT1h, *pXT1l, *pZh, *pZl, *pW1h, *pW1l, *pW2h, *pW2l;
    static float *pC1, *pC2;
    static bool init_done = false;
    if (!init_done) {
        cudaGetSymbolAddress((void**)&pXT1h, g_XT1h);
        cudaGetSymbolAddress((void**)&pXT1l, g_XT1l);
        cudaGetSymbolAddress((void**)&pZh,   g_Zh);
        cudaGetSymbolAddress((void**)&pZl,   g_Zl);
        cudaGetSymbolAddress((void**)&pW1h,  g_W1th);
        cudaGetSymbolAddress((void**)&pW1l,  g_W1tl);
        cudaGetSymbolAddress((void**)&pW2h,  g_W2ph);
        cudaGetSymbolAddress((void**)&pW2l,  g_W2pl);
        cudaGetSymbolAddress((void**)&pC1,   g_C1);
        cudaGetSymbolAddress((void**)&pC2,   g_C2);
        cudaFuncSetAttribute(mma_gemm_kernel,
                             cudaFuncAttributeMaxDynamicSharedMemorySize, GSMEM_TOTAL);
        init_done = true;
    }

    // E0: split inputs+cache into XT1 hi/lo
    build_xt1_kernel<<<ROWS, 256>>>(inputs, lf1);

    // Weight transposes + splits
    transpose_split_kernel<<<dim3(DDIM / 32, DDIM / 32), dim3(32, 8)>>>(W1, DDIM, DDIM, pW1h, pW1l);
    transpose_split_w2p_kernel<<<dim3(N2P / 32, K2 / 32), dim3(32, 8)>>>(W2);

    // G1: C1 = XT1 @ W1   [16392,2048]x[2048,2048]
    {
        dim3 grid(DDIM / 128, (ROWS + 127) / 128);   // 16 x 129
        mma_gemm_kernel<<<grid, 256, GSMEM_TOTAL>>>(pXT1h, pXT1l, pW1h, pW1l,
                                                    pC1, ROWS, DDIM, DDIM);
    }

    // E1: build Z hi/lo from C1 (conv-2 shift folded into GEMM2 operand)
    build_z_kernel<<<TOK, 256>>>(lf2, b1);

    // G2: C2 = Z @ W2'   [16384,2048]x[2048,2048]
    {
        dim3 grid(N2P / 128, TOK / 128);             // 16 x 128
        mma_gemm_kernel<<<grid, 256, GSMEM_TOTAL>>>(pZh, pZl, pW2h, pW2l,
                                                    pC2, TOK, K2, N2P);
    }

    // E2: epilogue (bias + residual + RMSNorm), row-local now
    epilogue_kernel<<<TOK, 256>>>(inputs, b2, lnw, out);
}

// round 10
// speedup vs baseline: 1.6257x; 1.4276x over previous
#include <cuda_runtime.h>
#include <cuda_bf16.h>
#include <cuda_fp16.h>
#include <cstdint>
#include <cstddef>

// Problem constants (fixed by setup_inputs: BS=8, L=2048, D=2048, CACHE=64)
#define BSQ   8
#define LSEQ  2048
#define TOK   16384          // BS*L
#define ROWS  16392          // TOK + BS (padded buffer rows)
#define DDIM  2048
#define H1    1024           // conv1 output width
#define K2    2048           // GEMM2 K after Z-concat
#define N2P   2048           // GEMM2 N after fold

// ---------------------------------------------------------------------------
// Device-global scratch (allocation-free path)
// fp16 2-term split: activations hi/lo fp16 (captures A to ~2^-23),
// weights single fp16 (the 2^-12 quantization is the only surviving error).
// ---------------------------------------------------------------------------
__device__ __half g_XT1h[(size_t)ROWS * DDIM];
__device__ __half g_XT1l[(size_t)ROWS * DDIM];
__device__ __half g_Zh[(size_t)TOK * K2];        // Z = [XT2[p], XT2[p+1]]
__device__ __half g_Zl[(size_t)TOK * K2];
__device__ __half g_W1t[(size_t)DDIM * DDIM];    // W1^T fp16 [N][K]
__device__ __half g_W2p[(size_t)N2P * K2];       // W2'^T fp16 [N][K]
__device__ float g_C1[(size_t)ROWS * DDIM];
__device__ float g_C2[(size_t)TOK * N2P];

// ---------------------------------------------------------------------------
// helpers
// ---------------------------------------------------------------------------
__device__ __forceinline__ uint32_t smem_u32(const void* p) {
    uint32_t a;
    asm("{ .reg .u64 t; cvta.to.shared.u64 t, %1; cvt.u32.u64 %0, t; }"
        : "=r"(a) : "l"(p));
    return a;
}
__device__ __forceinline__ void cp_async16(uint32_t dst, const void* src, uint32_t bytes) {
    asm volatile("cp.async.cg.shared.global [%0], [%1], 16, %2;"
                 :: "r"(dst), "l"(src), "r"(bytes) : "memory");
}
__device__ __forceinline__ void ldsm_x4(uint32_t& r0, uint32_t& r1,
                                        uint32_t& r2, uint32_t& r3, uint32_t addr) {
    asm volatile("ldmatrix.sync.aligned.m8n8.x4.shared.b16 {%0,%1,%2,%3}, [%4];"
                 : "=r"(r0), "=r"(r1), "=r"(r2), "=r"(r3) : "r"(addr));
}
__device__ __forceinline__ void mma_f16(float& c0, float& c1, float& c2, float& c3,
                                        uint32_t a0, uint32_t a1, uint32_t a2, uint32_t a3,
                                        uint32_t b0, uint32_t b1) {
    asm volatile(
        "mma.sync.aligned.m16n8k16.row.col.f32.f16.f16.f32 "
        "{%0,%1,%2,%3}, {%4,%5,%6,%7}, {%8,%9}, {%0,%1,%2,%3};"
        : "+f"(c0), "+f"(c1), "+f"(c2), "+f"(c3)
        : "r"(a0), "r"(a1), "r"(a2), "r"(a3), "r"(b0), "r"(b1));
}

// ---------------------------------------------------------------------------
// fp16 mma.sync GEMM: C[M,N] = A[M,K] * Bt[N,K]^T, 2-term fp16 split fused as
// 2 K-phases: (Ahi,B), (Alo,B) into the same accumulators (B reused -> L2 hits).
// Block tile 128x128x64, 8 warps (2x4), warp tile 64x32, 3-stage cp.async,
// ldmatrix fragment loads (144B pitch -> conflict-free), ONE sync per iter,
// producer issued after the first kk-chunk so MMAs start right post-barrier.
// ---------------------------------------------------------------------------
#define GS 3
#define PITCH 144
#define ATILE_B (128 * PITCH)          // 18432
#define STAGE_B (2 * ATILE_B)          // 36864
#define GSMEM_TOTAL (GS * STAGE_B)     // 110592

__global__ __launch_bounds__(256, 2)
void mma_gemm_kernel(const __half* __restrict__ Ahi,
                     const __half* __restrict__ Alo,
                     const __half* __restrict__ B,
                     float* __restrict__ C, int M, int K, int N)
{
    extern __shared__ char smem[];
    const uint32_t sbase = smem_u32(smem);
    const int tid  = threadIdx.x;
    const int wid  = tid >> 5;
    const int lane = tid & 31;
    const int wm   = wid & 1;          // 0..1
    const int wn   = wid >> 1;         // 0..3
    const int g    = lane >> 2;        // 0..7
    const int tig  = lane & 3;         // 0..3

    const int nbase = blockIdx.x * 128;
    const int mbase = blockIdx.y * 128;

    const int NK  = K >> 6;            // K tiles of 64
    const int TOT = 2 * NK;

    const __half* Aph[2] = {Ahi, Alo};

    // ldmatrix per-lane base offsets (within a stage's A / B region)
    const uint32_t aoff = (uint32_t)(wm * 64 + (lane & 7) + ((lane >> 3) & 1) * 8) * PITCH
                        + (uint32_t)(lane >> 4) * 16;
    const uint32_t boff = (uint32_t)(wn * 32 + ((lane >> 4) & 1) * 8 + (lane & 7)) * PITCH
                        + (uint32_t)((lane >> 3) & 1) * 16;

    auto produce = [&](int pi) {
        const int st = pi % GS;
        const int ph = pi / NK;
        const int kk = (pi - ph * NK) << 6;
        const __half* Ap = Aph[ph];
        const uint32_t sA = sbase + st * STAGE_B;
        const uint32_t sB = sA + ATILE_B;
        #pragma unroll
        for (int h = 0; h < 4; h++) {
            int c  = tid + h * 256;
            int r  = c >> 3;
            int cc = c & 7;
            int grow = mbase + r;
            uint32_t ok = (grow < M) ? 16u : 0u;
            const void* srcA = Ap + ((size_t)(ok ? grow : 0) * K + kk + cc * 8);
            cp_async16(sA + r * PITCH + cc * 16, srcA, ok);
            const void* srcB = B + ((size_t)(nbase + r) * K + kk + cc * 8);
            cp_async16(sB + r * PITCH + cc * 16, srcB, 16u);
        }
        asm volatile("cp.async.commit_group;" ::: "memory");
    };

    float acc[4][4][4];
    #pragma unroll
    for (int mt = 0; mt < 4; mt++)
        #pragma unroll
        for (int nt = 0; nt < 4; nt++)
            #pragma unroll
            for (int e = 0; e < 4; e++)
                acc[mt][nt][e] = 0.f;

    // prologue: prefetch GS-1 stages
    produce(0); produce(1);

    for (int it = 0; it < TOT; it++) {
        asm volatile("cp.async.wait_group 1;" ::: "memory");
        __syncthreads();

        const int st = it % GS;
        const uint32_t sA = sbase + st * STAGE_B;
        const uint32_t sB = sA + ATILE_B;

        auto do_chunk = [&](int kk) {
            uint32_t bf[4][2];
            #pragma unroll
            for (int np = 0; np < 2; np++) {
                ldsm_x4(bf[2 * np][0], bf[2 * np][1],
                        bf[2 * np + 1][0], bf[2 * np + 1][1],
                        sB + boff + (uint32_t)np * (16 * PITCH) + (uint32_t)kk * 2);
            }
            #pragma unroll
            for (int mt = 0; mt < 4; mt++) {
                uint32_t a0, a1, a2, a3;
                ldsm_x4(a0, a1, a2, a3,
                        sA + aoff + (uint32_t)mt * (16 * PITCH) + (uint32_t)kk * 2);
                #pragma unroll
                for (int nt = 0; nt < 4; nt++)
                    mma_f16(acc[mt][nt][0], acc[mt][nt][1],
                            acc[mt][nt][2], acc[mt][nt][3],
                            a0, a1, a2, a3, bf[nt][0], bf[nt][1]);
            }
        };

        do_chunk(0);
        if (it + 2 < TOT) produce(it + 2);   // writes stage (it+2)%3 != it%3
        do_chunk(16);
        do_chunk(32);
        do_chunk(48);
    }

    // store
    #pragma unroll
    for (int mt = 0; mt < 4; mt++) {
        int row = mbase + wm * 64 + mt * 16 + g;
        #pragma unroll
        for (int nt = 0; nt < 4; nt++) {
            int col = nbase + wn * 32 + nt * 8 + tig * 2;
            if (row < M) {
                float2 v = make_float2(acc[mt][nt][0], acc[mt][nt][1]);
                *(float2*)(C + (size_t)row * N + col) = v;
            }
            if (row + 8 < M) {
                float2 v = make_float2(acc[mt][nt][2], acc[mt][nt][3]);
                *(float2*)(C + (size_t)(row + 8) * N + col) = v;
            }
        }
    }
}

// ---------------------------------------------------------------------------
// E0: build XT1 hi/lo (fp16) from inputs/lf1 (p = s*2049+j; j==0 -> cache row)
// ---------------------------------------------------------------------------
__global__ void build_xt1_kernel(const float* __restrict__ inputs,
                                 const float* __restrict__ lf1)
{
    int p = blockIdx.x;
    int s = p / (LSEQ + 1);
    int j = p - s * (LSEQ + 1);
    const float* src = (j == 0)
        ? (lf1 + (size_t)s * DDIM)
        : (inputs + ((size_t)s * LSEQ + (j - 1)) * DDIM);
    __half* dh = g_XT1h + (size_t)p * DDIM;
    __half* dl = g_XT1l + (size_t)p * DDIM;
    int base = threadIdx.x * 8;
    #pragma unroll
    for (int v = 0; v < 2; v++) {
        float4 x = *(const float4*)(src + base + v * 4);
        float xs[4] = {x.x, x.y, x.z, x.w};
        #pragma unroll
        for (int e = 0; e < 4; e++) {
            __half h = __float2half_rn(xs[e]);
            dh[base + v * 4 + e] = h;
            dl[base + v * 4 + e] = __float2half_rn(xs[e] - __half2float(h));
        }
    }
}

// ---------------------------------------------------------------------------
// E1: build Z[t] = [ XT2[p] , XT2[p+1] ]  (p = s*2049 + j for token t=(s,j))
//   XT2[q] = (q at j==0) ? lf2[s] : C1[q-1,:1024] + C1[q,1024:] + b1
// one block per token, 256 threads: 4 cols per half per thread
// ---------------------------------------------------------------------------
__global__ void build_z_kernel(const float* __restrict__ lf2,
                               const float* __restrict__ b1)
{
    int t = blockIdx.x;
    int s = t >> 11;
    int j = t & 2047;
    size_t p = (size_t)s * (LSEQ + 1) + j;

    __half* zh = g_Zh + (size_t)t * K2;
    __half* zl = g_Zl + (size_t)t * K2;
    int base = threadIdx.x * 4;
    float4 bi = *(const float4*)(b1 + base);

    // half 1: XT2[p]
    float4 r1;
    if (j == 0) {
        r1 = *(const float4*)(lf2 + (size_t)s * H1 + base);
    } else {
        float4 a = *(const float4*)(g_C1 + (p - 1) * DDIM + base);
        float4 b = *(const float4*)(g_C1 + p * DDIM + H1 + base);
        r1.x = a.x + b.x + bi.x;  r1.y = a.y + b.y + bi.y;
        r1.z = a.z + b.z + bi.z;  r1.w = a.w + b.w + bi.w;
    }
    // half 2: XT2[p+1] (always the conv path; p+1 has j>=1)
    float4 a2 = *(const float4*)(g_C1 + p * DDIM + base);
    float4 b2 = *(const float4*)(g_C1 + (p + 1) * DDIM + H1 + base);
    float4 r2;
    r2.x = a2.x + b2.x + bi.x;  r2.y = a2.y + b2.y + bi.y;
    r2.z = a2.z + b2.z + bi.z;  r2.w = a2.w + b2.w + bi.w;

    float h1[4] = {r1.x, r1.y, r1.z, r1.w};
    float h2[4] = {r2.x, r2.y, r2.z, r2.w};
    #pragma unroll
    for (int e = 0; e < 4; e++) {
        __half hh = __float2half_rn(h1[e]);
        zh[base + e] = hh;
        zl[base + e] = __float2half_rn(h1[e] - __half2float(hh));
        __half hh2 = __float2half_rn(h2[e]);
        zh[H1 + base + e] = hh2;
        zl[H1 + base + e] = __float2half_rn(h2[e] - __half2float(hh2));
    }
}

// ---------------------------------------------------------------------------
// Transpose W1 -> fp16: g_W1t[c][r] = fp16(W[r][c]);  W is [R, Cc]
// ---------------------------------------------------------------------------
__global__ void transpose_w1_kernel(const float* __restrict__ W, int R, int Cc)
{
    __shared__ float t[32][33];
    int tx = threadIdx.x, ty = threadIdx.y;           // 32 x 8
    int r0 = blockIdx.y * 32, c0 = blockIdx.x * 32;
    #pragma unroll
    for (int k = 0; k < 4; k++)
        t[ty + 8 * k][tx] = W[(size_t)(r0 + ty + 8 * k) * Cc + c0 + tx];
    __syncthreads();
    #pragma unroll
    for (int k = 0; k < 4; k++) {
        int c = c0 + ty + 8 * k;
        int r = r0 + tx;
        g_W1t[(size_t)c * R + r] = __float2half_rn(t[tx][ty + 8 * k]);
    }
}

// ---------------------------------------------------------------------------
// Transpose W2' -> fp16: g_W2p[n][k'] (2048x2048), where
//   k' < 1024: W2[k'][n] ; k' >= 1024: W2[k'-1024][2048+n]   (W2 is [1024][4096])
// ---------------------------------------------------------------------------
__global__ void transpose_w2p_kernel(const float* __restrict__ W2)
{
    __shared__ float t[32][33];
    int tx = threadIdx.x, ty = threadIdx.y;           // 32 x 8
    int k0 = blockIdx.y * 32, n0 = blockIdx.x * 32;
    int half = k0 >> 10;
    int kr0  = k0 & 1023;
    #pragma unroll
    for (int u = 0; u < 4; u++)
        t[ty + 8 * u][tx] = W2[(size_t)(kr0 + ty + 8 * u) * 4096 + half * 2048 + n0 + tx];
    __syncthreads();
    #pragma unroll
    for (int u = 0; u < 4; u++) {
        int n = n0 + ty + 8 * u;
        int k = k0 + tx;
        g_W2p[(size_t)n * K2 + k] = __float2half_rn(t[tx][ty + 8 * u]);
    }
}

// ---------------------------------------------------------------------------
// E2: epilogue, row-local: out[t] = rmsnorm(C2[t] + b2 + inputs[t])
// ---------------------------------------------------------------------------
__global__ void epilogue_kernel(const float* __restrict__ inputs,
                                const float* __restrict__ b2,
                                const float* __restrict__ lnw,
                                float* __restrict__ out)
{
    int t = blockIdx.x;
    const float* rowA = g_C2 + (size_t)t * N2P;
    const float* xin  = inputs + (size_t)t * DDIM;

    int base = threadIdx.x * 8;
    float o[8];
    float ss = 0.f;
    #pragma unroll
    for (int v = 0; v < 2; v++) {
        float4 a  = *(const float4*)(rowA + base + v * 4);
        float4 bi = *(const float4*)(b2   + base + v * 4);
        float4 xi = *(const float4*)(xin  + base + v * 4);
        float r0 = a.x + bi.x + xi.x;
        float r1 = a.y + bi.y + xi.y;
        float r2 = a.z + bi.z + xi.z;
        float r3 = a.w + bi.w + xi.w;
        o[v * 4 + 0] = r0; o[v * 4 + 1] = r1; o[v * 4 + 2] = r2; o[v * 4 + 3] = r3;
        ss += r0 * r0 + r1 * r1 + r2 * r2 + r3 * r3;
    }

    __shared__ float red[8];
    #pragma unroll
    for (int off = 16; off > 0; off >>= 1)
        ss += __shfl_xor_sync(0xFFFFFFFFu, ss, off);
    int lane = threadIdx.x & 31;
    int wid  = threadIdx.x >> 5;
    if (lane == 0) red[wid] = ss;
    __syncthreads();
    float total = 0.f;
    #pragma unroll
    for (int w = 0; w < 8; w++) total += red[w];

    float scale = rsqrtf(total * (1.0f / DDIM) + 1e-6f);

    float* op = out + (size_t)t * DDIM;
    #pragma unroll
    for (int v = 0; v < 2; v++) {
        float4 lw = *(const float4*)(lnw + base + v * 4);
        float4 r;
        r.x = o[v * 4 + 0] * scale * lw.x;
        r.y = o[v * 4 + 1] * scale * lw.y;
        r.z = o[v * 4 + 2] * scale * lw.z;
        r.w = o[v * 4 + 3] * scale * lw.w;
        *(float4*)(op + base + v * 4) = r;
    }
}

// ---------------------------------------------------------------------------
// kernel_launch
// ---------------------------------------------------------------------------
extern "C" void kernel_launch(void* const* d_in, const int* in_sizes, int n_in,
                              void* d_out, int out_size)
{
    const float* inputs = (const float*)d_in[0];
    const float* lf1    = (const float*)d_in[7];
    const float* lf2    = (const float*)d_in[8];
    const float* W1     = (const float*)d_in[9];
    const float* W2     = (const float*)d_in[10];
    const float* b1     = (const float*)d_in[11];
    const float* b2     = (const float*)d_in[12];
    const float* lnw    = (const float*)d_in[13];
    float* out          = (float*)d_out;

    static __half *pXT1h, *pXT1l, *pZh, *pZl, *pW1, *pW2;
    static float *pC1, *pC2;
    static bool init_done = false;
    if (!init_done) {
        cudaGetSymbolAddress((void**)&pXT1h, g_XT1h);
        cudaGetSymbolAddress((void**)&pXT1l, g_XT1l);
        cudaGetSymbolAddress((void**)&pZh,   g_Zh);
        cudaGetSymbolAddress((void**)&pZl,   g_Zl);
        cudaGetSymbolAddress((void**)&pW1,   g_W1t);
        cudaGetSymbolAddress((void**)&pW2,   g_W2p);
        cudaGetSymbolAddress((void**)&pC1,   g_C1);
        cudaGetSymbolAddress((void**)&pC2,   g_C2);
        cudaFuncSetAttribute(mma_gemm_kernel,
                             cudaFuncAttributeMaxDynamicSharedMemorySize, GSMEM_TOTAL);
        init_done = true;
    }

    // E0: split inputs+cache into XT1 hi/lo (fp16)
    build_xt1_kernel<<<ROWS, 256>>>(inputs, lf1);

    // Weight transposes (single fp16)
    transpose_w1_kernel<<<dim3(DDIM / 32, DDIM / 32), dim3(32, 8)>>>(W1, DDIM, DDIM);
    transpose_w2p_kernel<<<dim3(N2P / 32, K2 / 32), dim3(32, 8)>>>(W2);

    // G1: C1 = XT1 @ W1   [16392,2048]x[2048,2048], 2 phases
    {
        dim3 grid(DDIM / 128, (ROWS + 127) / 128);   // 16 x 129
        mma_gemm_kernel<<<grid, 256, GSMEM_TOTAL>>>(pXT1h, pXT1l, pW1,
                                                    pC1, ROWS, DDIM, DDIM);
    }

    // E1: build Z hi/lo from C1 (conv-2 shift folded into GEMM2 operand)
    build_z_kernel<<<TOK, 256>>>(lf2, b1);

    // G2: C2 = Z @ W2'   [16384,2048]x[2048,2048], 2 phases
    {
        dim3 grid(N2P / 128, TOK / 128);             // 16 x 128
        mma_gemm_kernel<<<grid, 256, GSMEM_TOTAL>>>(pZh, pZl, pW2,
                                                    pC2, TOK, K2, N2P);
    }

    // E2: epilogue (bias + residual + RMSNorm), row-local now
    epilogue_kernel<<<TOK, 256>>>(inputs, b2, lnw, out);
}

// round 13
// speedup vs baseline: 3.4275x; 2.1084x over previous
#include <cuda_runtime.h>
#include <cuda_bf16.h>
#include <cuda_fp16.h>
#include <cstdint>
#include <cstddef>

// Problem constants (fixed by setup_inputs: BS=8, L=2048, D=2048, CACHE=64)
#define BSQ   8
#define LSEQ  2048
#define TOK   16384          // BS*L
#define ROWS  16392          // TOK + BS (padded buffer rows)
#define DDIM  2048
#define H1    1024           // conv1 output width
#define K2    2048           // GEMM2 K after Z-concat
#define N2P   2048           // GEMM2 N after fold

// ---------------------------------------------------------------------------
// Device-global scratch (allocation-free path)
// Single fp16 operands both sides: per-layer quantization error ~2e-4,
// chained ~3e-4 (validated error model, 3x margin under 1e-3 tolerance).
// ---------------------------------------------------------------------------
__device__ __half g_XT1[(size_t)ROWS * DDIM];
__device__ __half g_Z[(size_t)TOK * K2];         // Z = [XT2[p], XT2[p+1]]
__device__ __half g_W1t[(size_t)DDIM * DDIM];    // W1^T fp16 [N][K]
__device__ __half g_W2p[(size_t)N2P * K2];       // W2'^T fp16 [N][K]
__device__ float g_C1[(size_t)ROWS * DDIM];
__device__ float g_C2[(size_t)TOK * N2P];

// ---------------------------------------------------------------------------
// helpers
// ---------------------------------------------------------------------------
__device__ __forceinline__ uint32_t smem_u32(const void* p) {
    uint32_t a;
    asm("{ .reg .u64 t; cvta.to.shared.u64 t, %1; cvt.u32.u64 %0, t; }"
        : "=r"(a) : "l"(p));
    return a;
}
__device__ __forceinline__ void cp_async16(uint32_t dst, const void* src, uint32_t bytes) {
    asm volatile("cp.async.cg.shared.global [%0], [%1], 16, %2;"
                 :: "r"(dst), "l"(src), "r"(bytes) : "memory");
}
__device__ __forceinline__ void ldsm_x4(uint32_t& r0, uint32_t& r1,
                                        uint32_t& r2, uint32_t& r3, uint32_t addr) {
    asm volatile("ldmatrix.sync.aligned.m8n8.x4.shared.b16 {%0,%1,%2,%3}, [%4];"
                 : "=r"(r0), "=r"(r1), "=r"(r2), "=r"(r3) : "r"(addr));
}
__device__ __forceinline__ void mma_f16(float& c0, float& c1, float& c2, float& c3,
                                        uint32_t a0, uint32_t a1, uint32_t a2, uint32_t a3,
                                        uint32_t b0, uint32_t b1) {
    asm volatile(
        "mma.sync.aligned.m16n8k16.row.col.f32.f16.f16.f32 "
        "{%0,%1,%2,%3}, {%4,%5,%6,%7}, {%8,%9}, {%0,%1,%2,%3};"
        : "+f"(c0), "+f"(c1), "+f"(c2), "+f"(c3)
        : "r"(a0), "r"(a1), "r"(a2), "r"(a3), "r"(b0), "r"(b1));
}

// ---------------------------------------------------------------------------
// fp16 mma.sync GEMM: C[M,N] = A[M,K] * Bt[N,K]^T, single phase.
// Block tile 128x128x64, 8 warps (2x4), warp tile 64x32, 3-stage cp.async,
// ldmatrix fragment loads (144B pitch -> conflict-free), ONE sync per iter,
// producer issued after the first kk-chunk so MMAs start right post-barrier.
// ---------------------------------------------------------------------------
#define GS 3
#define PITCH 144
#define ATILE_B (128 * PITCH)          // 18432
#define STAGE_B (2 * ATILE_B)          // 36864
#define GSMEM_TOTAL (GS * STAGE_B)     // 110592

__global__ __launch_bounds__(256, 2)
void mma_gemm_kernel(const __half* __restrict__ A,
                     const __half* __restrict__ B,
                     float* __restrict__ C, int M, int K, int N)
{
    extern __shared__ char smem[];
    const uint32_t sbase = smem_u32(smem);
    const int tid  = threadIdx.x;
    const int wid  = tid >> 5;
    const int lane = tid & 31;
    const int wm   = wid & 1;          // 0..1
    const int wn   = wid >> 1;         // 0..3
    const int g    = lane >> 2;        // 0..7
    const int tig  = lane & 3;         // 0..3

    const int nbase = blockIdx.x * 128;
    const int mbase = blockIdx.y * 128;

    const int TOT = K >> 6;            // K tiles of 64

    // ldmatrix per-lane base offsets (within a stage's A / B region)
    const uint32_t aoff = (uint32_t)(wm * 64 + (lane & 7) + ((lane >> 3) & 1) * 8) * PITCH
                        + (uint32_t)(lane >> 4) * 16;
    const uint32_t boff = (uint32_t)(wn * 32 + ((lane >> 4) & 1) * 8 + (lane & 7)) * PITCH
                        + (uint32_t)((lane >> 3) & 1) * 16;

    auto produce = [&](int pi) {
        const int st = pi % GS;
        const int kk = pi << 6;
        const uint32_t sA = sbase + st * STAGE_B;
        const uint32_t sB = sA + ATILE_B;
        #pragma unroll
        for (int h = 0; h < 4; h++) {
            int c  = tid + h * 256;
            int r  = c >> 3;
            int cc = c & 7;
            int grow = mbase + r;
            uint32_t ok = (grow < M) ? 16u : 0u;
            const void* srcA = A + ((size_t)(ok ? grow : 0) * K + kk + cc * 8);
            cp_async16(sA + r * PITCH + cc * 16, srcA, ok);
            const void* srcB = B + ((size_t)(nbase + r) * K + kk + cc * 8);
            cp_async16(sB + r * PITCH + cc * 16, srcB, 16u);
        }
        asm volatile("cp.async.commit_group;" ::: "memory");
    };

    float acc[4][4][4];
    #pragma unroll
    for (int mt = 0; mt < 4; mt++)
        #pragma unroll
        for (int nt = 0; nt < 4; nt++)
            #pragma unroll
            for (int e = 0; e < 4; e++)
                acc[mt][nt][e] = 0.f;

    // prologue: prefetch GS-1 stages
    produce(0); produce(1);

    for (int it = 0; it < TOT; it++) {
        asm volatile("cp.async.wait_group 1;" ::: "memory");
        __syncthreads();

        const int st = it % GS;
        const uint32_t sA = sbase + st * STAGE_B;
        const uint32_t sB = sA + ATILE_B;

        auto do_chunk = [&](int kk) {
            uint32_t bf[4][2];
            #pragma unroll
            for (int np = 0; np < 2; np++) {
                ldsm_x4(bf[2 * np][0], bf[2 * np][1],
                        bf[2 * np + 1][0], bf[2 * np + 1][1],
                        sB + boff + (uint32_t)np * (16 * PITCH) + (uint32_t)kk * 2);
            }
            #pragma unroll
            for (int mt = 0; mt < 4; mt++) {
                uint32_t a0, a1, a2, a3;
                ldsm_x4(a0, a1, a2, a3,
                        sA + aoff + (uint32_t)mt * (16 * PITCH) + (uint32_t)kk * 2);
                #pragma unroll
                for (int nt = 0; nt < 4; nt++)
                    mma_f16(acc[mt][nt][0], acc[mt][nt][1],
                            acc[mt][nt][2], acc[mt][nt][3],
                            a0, a1, a2, a3, bf[nt][0], bf[nt][1]);
            }
        };

        do_chunk(0);
        if (it + 2 < TOT) produce(it + 2);   // writes stage (it+2)%3 != it%3
        do_chunk(16);
        do_chunk(32);
        do_chunk(48);
    }

    // store
    #pragma unroll
    for (int mt = 0; mt < 4; mt++) {
        int row = mbase + wm * 64 + mt * 16 + g;
        #pragma unroll
        for (int nt = 0; nt < 4; nt++) {
            int col = nbase + wn * 32 + nt * 8 + tig * 2;
            if (row < M) {
                float2 v = make_float2(acc[mt][nt][0], acc[mt][nt][1]);
                *(float2*)(C + (size_t)row * N + col) = v;
            }
            if (row + 8 < M) {
                float2 v = make_float2(acc[mt][nt][2], acc[mt][nt][3]);
                *(float2*)(C + (size_t)(row + 8) * N + col) = v;
            }
        }
    }
}

// ---------------------------------------------------------------------------
// E0: build XT1 (fp16) from inputs/lf1 (p = s*2049+j; j==0 -> cache row)
// ---------------------------------------------------------------------------
__global__ void build_xt1_kernel(const float* __restrict__ inputs,
                                 const float* __restrict__ lf1)
{
    int p = blockIdx.x;
    int s = p / (LSEQ + 1);
    int j = p - s * (LSEQ + 1);
    const float* src = (j == 0)
        ? (lf1 + (size_t)s * DDIM)
        : (inputs + ((size_t)s * LSEQ + (j - 1)) * DDIM);
    __half* dh = g_XT1 + (size_t)p * DDIM;
    int base = threadIdx.x * 8;
    #pragma unroll
    for (int v = 0; v < 2; v++) {
        float4 x = *(const float4*)(src + base + v * 4);
        __half2 h0 = make_half2(__float2half_rn(x.x), __float2half_rn(x.y));
        __half2 h1 = make_half2(__float2half_rn(x.z), __float2half_rn(x.w));
        *(__half2*)(dh + base + v * 4)     = h0;
        *(__half2*)(dh + base + v * 4 + 2) = h1;
    }
}

// ---------------------------------------------------------------------------
// E1: build Z[t] = [ XT2[p] , XT2[p+1] ]  (p = s*2049 + j for token t=(s,j))
//   XT2[q] = (q at j==0) ? lf2[s] : C1[q-1,:1024] + C1[q,1024:] + b1
// one block per token, 256 threads: 4 cols per half per thread
// ---------------------------------------------------------------------------
__global__ void build_z_kernel(const float* __restrict__ lf2,
                               const float* __restrict__ b1)
{
    int t = blockIdx.x;
    int s = t >> 11;
    int j = t & 2047;
    size_t p = (size_t)s * (LSEQ + 1) + j;

    __half* z = g_Z + (size_t)t * K2;
    int base = threadIdx.x * 4;
    float4 bi = *(const float4*)(b1 + base);

    // half 1: XT2[p]
    float4 r1;
    if (j == 0) {
        r1 = *(const float4*)(lf2 + (size_t)s * H1 + base);
    } else {
        float4 a = *(const float4*)(g_C1 + (p - 1) * DDIM + base);
        float4 b = *(const float4*)(g_C1 + p * DDIM + H1 + base);
        r1.x = a.x + b.x + bi.x;  r1.y = a.y + b.y + bi.y;
        r1.z = a.z + b.z + bi.z;  r1.w = a.w + b.w + bi.w;
    }
    // half 2: XT2[p+1] (always the conv path; p+1 has j>=1)
    float4 a2 = *(const float4*)(g_C1 + p * DDIM + base);
    float4 b2 = *(const float4*)(g_C1 + (p + 1) * DDIM + H1 + base);
    float4 r2;
    r2.x = a2.x + b2.x + bi.x;  r2.y = a2.y + b2.y + bi.y;
    r2.z = a2.z + b2.z + bi.z;  r2.w = a2.w + b2.w + bi.w;

    *(__half2*)(z + base)          = make_half2(__float2half_rn(r1.x), __float2half_rn(r1.y));
    *(__half2*)(z + base + 2)      = make_half2(__float2half_rn(r1.z), __float2half_rn(r1.w));
    *(__half2*)(z + H1 + base)     = make_half2(__float2half_rn(r2.x), __float2half_rn(r2.y));
    *(__half2*)(z + H1 + base + 2) = make_half2(__float2half_rn(r2.z), __float2half_rn(r2.w));
}

// ---------------------------------------------------------------------------
// Transpose W1 -> fp16: g_W1t[c][r] = fp16(W[r][c]);  W is [R, Cc]
// ---------------------------------------------------------------------------
__global__ void transpose_w1_kernel(const float* __restrict__ W, int R, int Cc)
{
    __shared__ float t[32][33];
    int tx = threadIdx.x, ty = threadIdx.y;           // 32 x 8
    int r0 = blockIdx.y * 32, c0 = blockIdx.x * 32;
    #pragma unroll
    for (int k = 0; k < 4; k++)
        t[ty + 8 * k][tx] = W[(size_t)(r0 + ty + 8 * k) * Cc + c0 + tx];
    __syncthreads();
    #pragma unroll
    for (int k = 0; k < 4; k++) {
        int c = c0 + ty + 8 * k;
        int r = r0 + tx;
        g_W1t[(size_t)c * R + r] = __float2half_rn(t[tx][ty + 8 * k]);
    }
}

// ---------------------------------------------------------------------------
// Transpose W2' -> fp16: g_W2p[n][k'] (2048x2048), where
//   k' < 1024: W2[k'][n] ; k' >= 1024: W2[k'-1024][2048+n]   (W2 is [1024][4096])
// ---------------------------------------------------------------------------
__global__ void transpose_w2p_kernel(const float* __restrict__ W2)
{
    __shared__ float t[32][33];
    int tx = threadIdx.x, ty = threadIdx.y;           // 32 x 8
    int k0 = blockIdx.y * 32, n0 = blockIdx.x * 32;
    int half = k0 >> 10;
    int kr0  = k0 & 1023;
    #pragma unroll
    for (int u = 0; u < 4; u++)
        t[ty + 8 * u][tx] = W2[(size_t)(kr0 + ty + 8 * u) * 4096 + half * 2048 + n0 + tx];
    __syncthreads();
    #pragma unroll
    for (int u = 0; u < 4; u++) {
        int n = n0 + ty + 8 * u;
        int k = k0 + tx;
        g_W2p[(size_t)n * K2 + k] = __float2half_rn(t[tx][ty + 8 * u]);
    }
}

// ---------------------------------------------------------------------------
// E2: epilogue, row-local: out[t] = rmsnorm(C2[t] + b2 + inputs[t])
// ---------------------------------------------------------------------------
__global__ void epilogue_kernel(const float* __restrict__ inputs,
                                const float* __restrict__ b2,
                                const float* __restrict__ lnw,
                                float* __restrict__ out)
{
    int t = blockIdx.x;
    const float* rowA = g_C2 + (size_t)t * N2P;
    const float* xin  = inputs + (size_t)t * DDIM;

    int base = threadIdx.x * 8;
    float o[8];
    float ss = 0.f;
    #pragma unroll
    for (int v = 0; v < 2; v++) {
        float4 a  = *(const float4*)(rowA + base + v * 4);
        float4 bi = *(const float4*)(b2   + base + v * 4);
        float4 xi = *(const float4*)(xin  + base + v * 4);
        float r0 = a.x + bi.x + xi.x;
        float r1 = a.y + bi.y + xi.y;
        float r2 = a.z + bi.z + xi.z;
        float r3 = a.w + bi.w + xi.w;
        o[v * 4 + 0] = r0; o[v * 4 + 1] = r1; o[v * 4 + 2] = r2; o[v * 4 + 3] = r3;
        ss += r0 * r0 + r1 * r1 + r2 * r2 + r3 * r3;
    }

    __shared__ float red[8];
    #pragma unroll
    for (int off = 16; off > 0; off >>= 1)
        ss += __shfl_xor_sync(0xFFFFFFFFu, ss, off);
    int lane = threadIdx.x & 31;
    int wid  = threadIdx.x >> 5;
    if (lane == 0) red[wid] = ss;
    __syncthreads();
    float total = 0.f;
    #pragma unroll
    for (int w = 0; w < 8; w++) total += red[w];

    float scale = rsqrtf(total * (1.0f / DDIM) + 1e-6f);

    float* op = out + (size_t)t * DDIM;
    #pragma unroll
    for (int v = 0; v < 2; v++) {
        float4 lw = *(const float4*)(lnw + base + v * 4);
        float4 r;
        r.x = o[v * 4 + 0] * scale * lw.x;
        r.y = o[v * 4 + 1] * scale * lw.y;
        r.z = o[v * 4 + 2] * scale * lw.z;
        r.w = o[v * 4 + 3] * scale * lw.w;
        *(float4*)(op + base + v * 4) = r;
    }
}

// ---------------------------------------------------------------------------
// kernel_launch
// ---------------------------------------------------------------------------
extern "C" void kernel_launch(void* const* d_in, const int* in_sizes, int n_in,
                              void* d_out, int out_size)
{
    const float* inputs = (const float*)d_in[0];
    const float* lf1    = (const float*)d_in[7];
    const float* lf2    = (const float*)d_in[8];
    const float* W1     = (const float*)d_in[9];
    const float* W2     = (const float*)d_in[10];
    const float* b1     = (const float*)d_in[11];
    const float* b2     = (const float*)d_in[12];
    const float* lnw    = (const float*)d_in[13];
    float* out          = (float*)d_out;

    static __half *pXT1, *pZ, *pW1, *pW2;
    static float *pC1, *pC2;
    static bool init_done = false;
    if (!init_done) {
        cudaGetSymbolAddress((void**)&pXT1, g_XT1);
        cudaGetSymbolAddress((void**)&pZ,   g_Z);
        cudaGetSymbolAddress((void**)&pW1,  g_W1t);
        cudaGetSymbolAddress((void**)&pW2,  g_W2p);
        cudaGetSymbolAddress((void**)&pC1,  g_C1);
        cudaGetSymbolAddress((void**)&pC2,  g_C2);
        cudaFuncSetAttribute(mma_gemm_kernel,
                             cudaFuncAttributeMaxDynamicSharedMemorySize, GSMEM_TOTAL);
        init_done = true;
    }

    // E0: XT1 (fp16)
    build_xt1_kernel<<<ROWS, 256>>>(inputs, lf1);

    // Weight transposes (single fp16)
    transpose_w1_kernel<<<dim3(DDIM / 32, DDIM / 32), dim3(32, 8)>>>(W1, DDIM, DDIM);
    transpose_w2p_kernel<<<dim3(N2P / 32, K2 / 32), dim3(32, 8)>>>(W2);

    // G1: C1 = XT1 @ W1   [16392,2048]x[2048,2048], single phase
    {
        dim3 grid(DDIM / 128, (ROWS + 127) / 128);   // 16 x 129
        mma_gemm_kernel<<<grid, 256, GSMEM_TOTAL>>>(pXT1, pW1, pC1, ROWS, DDIM, DDIM);
    }

    // E1: build Z from C1 (conv-2 shift folded into GEMM2 operand)
    build_z_kernel<<<TOK, 256>>>(lf2, b1);

    // G2: C2 = Z @ W2'   [16384,2048]x[2048,2048], single phase
    {
        dim3 grid(N2P / 128, TOK / 128);             // 16 x 128
        mma_gemm_kernel<<<grid, 256, GSMEM_TOTAL>>>(pZ, pW2, pC2, TOK, K2, N2P);
    }

    // E2: epilogue (bias + residual + RMSNorm), row-local now
    epilogue_kernel<<<TOK, 256>>>(inputs, b2, lnw, out);
}

// round 14
// speedup vs baseline: 3.6552x; 1.0665x over previous
#include <cuda_runtime.h>
#include <cuda_bf16.h>
#include <cuda_fp16.h>
#include <cstdint>
#include <cstddef>

// Problem constants (fixed by setup_inputs: BS=8, L=2048, D=2048, CACHE=64)
#define BSQ   8
#define LSEQ  2048
#define TOK   16384          // BS*L
#define ROWS  16392          // TOK + BS (padded buffer rows)
#define DDIM  2048
#define H1    1024           // conv1 output width
#define K2    2048           // GEMM2 K after Z-concat
#define N2P   2048           // GEMM2 N after fold

// ---------------------------------------------------------------------------
// Device-global scratch (allocation-free path)
// ---------------------------------------------------------------------------
__device__ __half g_XT1[(size_t)ROWS * DDIM];
__device__ __half g_Z[(size_t)TOK * K2];         // Z = [XT2[p], XT2[p+1]]
__device__ __half g_W1t[(size_t)DDIM * DDIM];    // W1^T fp16 [N][K]
__device__ __half g_W2p[(size_t)N2P * K2];       // W2'^T fp16 [N][K]
__device__ float g_C1[(size_t)ROWS * DDIM];
__device__ float g_C2[(size_t)TOK * N2P];

// ---------------------------------------------------------------------------
// helpers
// ---------------------------------------------------------------------------
__device__ __forceinline__ uint32_t smem_u32(const void* p) {
    uint32_t a;
    asm("{ .reg .u64 t; cvta.to.shared.u64 t, %1; cvt.u32.u64 %0, t; }"
        : "=r"(a) : "l"(p));
    return a;
}
__device__ __forceinline__ void cp_async16(uint32_t dst, const void* src, uint32_t bytes) {
    asm volatile("cp.async.cg.shared.global [%0], [%1], 16, %2;"
                 :: "r"(dst), "l"(src), "r"(bytes) : "memory");
}
__device__ __forceinline__ void ldsm_x4(uint32_t& r0, uint32_t& r1,
                                        uint32_t& r2, uint32_t& r3, uint32_t addr) {
    asm volatile("ldmatrix.sync.aligned.m8n8.x4.shared.b16 {%0,%1,%2,%3}, [%4];"
                 : "=r"(r0), "=r"(r1), "=r"(r2), "=r"(r3) : "r"(addr));
}
__device__ __forceinline__ void mma_f16(float& c0, float& c1, float& c2, float& c3,
                                        uint32_t a0, uint32_t a1, uint32_t a2, uint32_t a3,
                                        uint32_t b0, uint32_t b1) {
    asm volatile(
        "mma.sync.aligned.m16n8k16.row.col.f32.f16.f16.f32 "
        "{%0,%1,%2,%3}, {%4,%5,%6,%7}, {%8,%9}, {%0,%1,%2,%3};"
        : "+f"(c0), "+f"(c1), "+f"(c2), "+f"(c3)
        : "r"(a0), "r"(a1), "r"(a2), "r"(a3), "r"(b0), "r"(b1));
}
__device__ __forceinline__ void mbar_wait(uint32_t mbar, uint32_t parity) {
    uint32_t done;
    asm volatile(
        "{\n\t.reg .pred p;\n\t"
        "mbarrier.try_wait.parity.acquire.cta.shared::cta.b64 p, [%1], %2;\n\t"
        "selp.b32 %0, 1, 0, p;\n\t}"
        : "=r"(done) : "r"(mbar), "r"(parity) : "memory");
    if (!done) {
        asm volatile(
            "{\n\t.reg .pred P1;\n\t"
            "WL_%=:\n\t"
            "mbarrier.try_wait.parity.acquire.cta.shared::cta.b64 P1, [%0], %1, 0x989680;\n\t"
            "@P1 bra.uni WD_%=;\n\t"
            "bra.uni WL_%=;\n\t"
            "WD_%=:\n\t}"
            :: "r"(mbar), "r"(parity) : "memory");
    }
}

// ---------------------------------------------------------------------------
// fp16 mma.sync GEMM: C[M,N] = A[M,K] * Bt[N,K]^T, single phase.
// Block tile 128x128x64, 8 warps (2x4), warp tile 64x32, 3-stage cp.async,
// DECOUPLED mbarrier pipeline (no block-wide barrier in the mainloop):
//   full[st]:  256 x cp.async.mbarrier.arrive.noinc (data landed)
//   empty[st]: 256 x mbarrier.arrive after last ldmatrix of the stage
// Warps tolerate one full iteration of skew -> tensor pipe stays fed.
// ---------------------------------------------------------------------------
#define GS 3
#define PITCH 144
#define ATILE_B (128 * PITCH)          // 18432
#define STAGE_B (2 * ATILE_B)          // 36864
#define GSMEM_TOTAL (GS * STAGE_B + 64)

__global__ __launch_bounds__(256, 2)
void mma_gemm_kernel(const __half* __restrict__ A,
                     const __half* __restrict__ B,
                     float* __restrict__ C, int M, int K, int N)
{
    extern __shared__ char smem[];
    const uint32_t sbase = smem_u32(smem);
    const uint32_t mb    = sbase + GS * STAGE_B;   // full[3] @ +0, empty[3] @ +32
    const int tid  = threadIdx.x;
    const int wid  = tid >> 5;
    const int lane = tid & 31;
    const int wm   = wid & 1;          // 0..1
    const int wn   = wid >> 1;         // 0..3
    const int g    = lane >> 2;        // 0..7
    const int tig  = lane & 3;         // 0..3

    const int nbase = blockIdx.x * 128;
    const int mbase = blockIdx.y * 128;

    const int TOT = K >> 6;            // K tiles of 64

    if (tid == 0) {
        #pragma unroll
        for (int s = 0; s < GS; s++) {
            asm volatile("mbarrier.init.shared.b64 [%0], %1;"
                         :: "r"(mb + s * 8), "r"(256u) : "memory");
            asm volatile("mbarrier.init.shared.b64 [%0], %1;"
                         :: "r"(mb + 32 + s * 8), "r"(256u) : "memory");
        }
    }
    __syncthreads();

    // ldmatrix per-lane base offsets (within a stage's A / B region)
    const uint32_t aoff = (uint32_t)(wm * 64 + (lane & 7) + ((lane >> 3) & 1) * 8) * PITCH
                        + (uint32_t)(lane >> 4) * 16;
    const uint32_t boff = (uint32_t)(wn * 32 + ((lane >> 4) & 1) * 8 + (lane & 7)) * PITCH
                        + (uint32_t)((lane >> 3) & 1) * 16;

    // producer state: stage pst, round pk (= pi/GS), K offset pkk
    int pst = 0, pk = 0;
    uint32_t pkk = 0;
    auto produce = [&]() {
        if (pk > 0) mbar_wait(mb + 32 + pst * 8, (uint32_t)((pk & 1) ^ 1));  // empty
        const uint32_t sA = sbase + pst * STAGE_B;
        const uint32_t sB = sA + ATILE_B;
        #pragma unroll
        for (int h = 0; h < 4; h++) {
            int c  = tid + h * 256;
            int r  = c >> 3;
            int cc = c & 7;
            int grow = mbase + r;
            uint32_t ok = (grow < M) ? 16u : 0u;
            const void* srcA = A + ((size_t)(ok ? grow : 0) * K + pkk + cc * 8);
            cp_async16(sA + r * PITCH + cc * 16, srcA, ok);
            const void* srcB = B + ((size_t)(nbase + r) * K + pkk + cc * 8);
            cp_async16(sB + r * PITCH + cc * 16, srcB, 16u);
        }
        asm volatile("cp.async.mbarrier.arrive.noinc.shared.b64 [%0];"
                     :: "r"(mb + pst * 8) : "memory");                        // full
        pkk += 64;
        if (++pst == GS) { pst = 0; pk++; }
    };

    float acc[4][4][4];
    #pragma unroll
    for (int mt = 0; mt < 4; mt++)
        #pragma unroll
        for (int nt = 0; nt < 4; nt++)
            #pragma unroll
            for (int e = 0; e < 4; e++)
                acc[mt][nt][e] = 0.f;

    // prologue: prefetch 2 stages
    produce(); produce();

    int cst = 0, ck = 0;
    for (int it = 0; it < TOT; it++) {
        mbar_wait(mb + cst * 8, (uint32_t)(ck & 1));    // full[cst], acquire

        const uint32_t sA = sbase + cst * STAGE_B;
        const uint32_t sB = sA + ATILE_B;

        auto do_chunk = [&](int kk) {
            uint32_t bf[4][2];
            #pragma unroll
            for (int np = 0; np < 2; np++) {
                ldsm_x4(bf[2 * np][0], bf[2 * np][1],
                        bf[2 * np + 1][0], bf[2 * np + 1][1],
                        sB + boff + (uint32_t)np * (16 * PITCH) + (uint32_t)kk * 2);
            }
            #pragma unroll
            for (int mt = 0; mt < 4; mt++) {
                uint32_t a0, a1, a2, a3;
                ldsm_x4(a0, a1, a2, a3,
                        sA + aoff + (uint32_t)mt * (16 * PITCH) + (uint32_t)kk * 2);
                #pragma unroll
                for (int nt = 0; nt < 4; nt++)
                    mma_f16(acc[mt][nt][0], acc[mt][nt][1],
                            acc[mt][nt][2], acc[mt][nt][3],
                            a0, a1, a2, a3, bf[nt][0], bf[nt][1]);
            }
        };

        do_chunk(0);
        if (it + 2 < TOT) produce();   // fills stage (it+2)%3, waits empty of it-1
        do_chunk(16);
        do_chunk(32);
        do_chunk(48);

        asm volatile("mbarrier.arrive.shared.b64 _, [%0];"
                     :: "r"(mb + 32 + cst * 8) : "memory");   // empty[cst], release
        if (++cst == GS) { cst = 0; ck++; }
    }

    // store
    #pragma unroll
    for (int mt = 0; mt < 4; mt++) {
        int row = mbase + wm * 64 + mt * 16 + g;
        #pragma unroll
        for (int nt = 0; nt < 4; nt++) {
            int col = nbase + wn * 32 + nt * 8 + tig * 2;
            if (row < M) {
                float2 v = make_float2(acc[mt][nt][0], acc[mt][nt][1]);
                *(float2*)(C + (size_t)row * N + col) = v;
            }
            if (row + 8 < M) {
                float2 v = make_float2(acc[mt][nt][2], acc[mt][nt][3]);
                *(float2*)(C + (size_t)(row + 8) * N + col) = v;
            }
        }
    }
}

// ---------------------------------------------------------------------------
// E0: build XT1 (fp16) from inputs/lf1 (p = s*2049+j; j==0 -> cache row)
// ---------------------------------------------------------------------------
__global__ void build_xt1_kernel(const float* __restrict__ inputs,
                                 const float* __restrict__ lf1)
{
    int p = blockIdx.x;
    int s = p / (LSEQ + 1);
    int j = p - s * (LSEQ + 1);
    const float* src = (j == 0)
        ? (lf1 + (size_t)s * DDIM)
        : (inputs + ((size_t)s * LSEQ + (j - 1)) * DDIM);
    __half* dh = g_XT1 + (size_t)p * DDIM;
    int base = threadIdx.x * 8;
    #pragma unroll
    for (int v = 0; v < 2; v++) {
        float4 x = *(const float4*)(src + base + v * 4);
        __half2 h0 = make_half2(__float2half_rn(x.x), __float2half_rn(x.y));
        __half2 h1 = make_half2(__float2half_rn(x.z), __float2half_rn(x.w));
        *(__half2*)(dh + base + v * 4)     = h0;
        *(__half2*)(dh + base + v * 4 + 2) = h1;
    }
}

// ---------------------------------------------------------------------------
// E1: build Z[t] = [ XT2[p] , XT2[p+1] ]  (p = s*2049 + j for token t=(s,j))
//   XT2[q] = (q at j==0) ? lf2[s] : C1[q-1,:1024] + C1[q,1024:] + b1
// ---------------------------------------------------------------------------
__global__ void build_z_kernel(const float* __restrict__ lf2,
                               const float* __restrict__ b1)
{
    int t = blockIdx.x;
    int s = t >> 11;
    int j = t & 2047;
    size_t p = (size_t)s * (LSEQ + 1) + j;

    __half* z = g_Z + (size_t)t * K2;
    int base = threadIdx.x * 4;
    float4 bi = *(const float4*)(b1 + base);

    // half 1: XT2[p]
    float4 r1;
    if (j == 0) {
        r1 = *(const float4*)(lf2 + (size_t)s * H1 + base);
    } else {
        float4 a = *(const float4*)(g_C1 + (p - 1) * DDIM + base);
        float4 b = *(const float4*)(g_C1 + p * DDIM + H1 + base);
        r1.x = a.x + b.x + bi.x;  r1.y = a.y + b.y + bi.y;
        r1.z = a.z + b.z + bi.z;  r1.w = a.w + b.w + bi.w;
    }
    // half 2: XT2[p+1] (always the conv path; p+1 has j>=1)
    float4 a2 = *(const float4*)(g_C1 + p * DDIM + base);
    float4 b2 = *(const float4*)(g_C1 + (p + 1) * DDIM + H1 + base);
    float4 r2;
    r2.x = a2.x + b2.x + bi.x;  r2.y = a2.y + b2.y + bi.y;
    r2.z = a2.z + b2.z + bi.z;  r2.w = a2.w + b2.w + bi.w;

    *(__half2*)(z + base)          = make_half2(__float2half_rn(r1.x), __float2half_rn(r1.y));
    *(__half2*)(z + base + 2)      = make_half2(__float2half_rn(r1.z), __float2half_rn(r1.w));
    *(__half2*)(z + H1 + base)     = make_half2(__float2half_rn(r2.x), __float2half_rn(r2.y));
    *(__half2*)(z + H1 + base + 2) = make_half2(__float2half_rn(r2.z), __float2half_rn(r2.w));
}

// ---------------------------------------------------------------------------
// Transpose W1 -> fp16: g_W1t[c][r] = fp16(W[r][c]);  W is [R, Cc]
// ---------------------------------------------------------------------------
__global__ void transpose_w1_kernel(const float* __restrict__ W, int R, int Cc)
{
    __shared__ float t[32][33];
    int tx = threadIdx.x, ty = threadIdx.y;           // 32 x 8
    int r0 = blockIdx.y * 32, c0 = blockIdx.x * 32;
    #pragma unroll
    for (int k = 0; k < 4; k++)
        t[ty + 8 * k][tx] = W[(size_t)(r0 + ty + 8 * k) * Cc + c0 + tx];
    __syncthreads();
    #pragma unroll
    for (int k = 0; k < 4; k++) {
        int c = c0 + ty + 8 * k;
        int r = r0 + tx;
        g_W1t[(size_t)c * R + r] = __float2half_rn(t[tx][ty + 8 * k]);
    }
}

// ---------------------------------------------------------------------------
// Transpose W2' -> fp16: g_W2p[n][k'] (2048x2048), where
//   k' < 1024: W2[k'][n] ; k' >= 1024: W2[k'-1024][2048+n]   (W2 is [1024][4096])
// ---------------------------------------------------------------------------
__global__ void transpose_w2p_kernel(const float* __restrict__ W2)
{
    __shared__ float t[32][33];
    int tx = threadIdx.x, ty = threadIdx.y;           // 32 x 8
    int k0 = blockIdx.y * 32, n0 = blockIdx.x * 32;
    int half = k0 >> 10;
    int kr0  = k0 & 1023;
    #pragma unroll
    for (int u = 0; u < 4; u++)
        t[ty + 8 * u][tx] = W2[(size_t)(kr0 + ty + 8 * u) * 4096 + half * 2048 + n0 + tx];
    __syncthreads();
    #pragma unroll
    for (int u = 0; u < 4; u++) {
        int n = n0 + ty + 8 * u;
        int k = k0 + tx;
        g_W2p[(size_t)n * K2 + k] = __float2half_rn(t[tx][ty + 8 * u]);
    }
}

// ---------------------------------------------------------------------------
// E2: epilogue, row-local: out[t] = rmsnorm(C2[t] + b2 + inputs[t])
// ---------------------------------------------------------------------------
__global__ void epilogue_kernel(const float* __restrict__ inputs,
                                const float* __restrict__ b2,
                                const float* __restrict__ lnw,
                                float* __restrict__ out)
{
    int t = blockIdx.x;
    const float* rowA = g_C2 + (size_t)t * N2P;
    const float* xin  = inputs + (size_t)t * DDIM;

    int base = threadIdx.x * 8;
    float o[8];
    float ss = 0.f;
    #pragma unroll
    for (int v = 0; v < 2; v++) {
        float4 a  = *(const float4*)(rowA + base + v * 4);
        float4 bi = *(const float4*)(b2   + base + v * 4);
        float4 xi = *(const float4*)(xin  + base + v * 4);
        float r0 = a.x + bi.x + xi.x;
        float r1 = a.y + bi.y + xi.y;
        float r2 = a.z + bi.z + xi.z;
        float r3 = a.w + bi.w + xi.w;
        o[v * 4 + 0] = r0; o[v * 4 + 1] = r1; o[v * 4 + 2] = r2; o[v * 4 + 3] = r3;
        ss += r0 * r0 + r1 * r1 + r2 * r2 + r3 * r3;
    }

    __shared__ float red[8];
    #pragma unroll
    for (int off = 16; off > 0; off >>= 1)
        ss += __shfl_xor_sync(0xFFFFFFFFu, ss, off);
    int lane = threadIdx.x & 31;
    int wid  = threadIdx.x >> 5;
    if (lane == 0) red[wid] = ss;
    __syncthreads();
    float total = 0.f;
    #pragma unroll
    for (int w = 0; w < 8; w++) total += red[w];

    float scale = rsqrtf(total * (1.0f / DDIM) + 1e-6f);

    float* op = out + (size_t)t * DDIM;
    #pragma unroll
    for (int v = 0; v < 2; v++) {
        float4 lw = *(const float4*)(lnw + base + v * 4);
        float4 r;
        r.x = o[v * 4 + 0] * scale * lw.x;
        r.y = o[v * 4 + 1] * scale * lw.y;
        r.z = o[v * 4 + 2] * scale * lw.z;
        r.w = o[v * 4 + 3] * scale * lw.w;
        *(float4*)(op + base + v * 4) = r;
    }
}

// ---------------------------------------------------------------------------
// kernel_launch
// ---------------------------------------------------------------------------
extern "C" void kernel_launch(void* const* d_in, const int* in_sizes, int n_in,
                              void* d_out, int out_size)
{
    const float* inputs = (const float*)d_in[0];
    const float* lf1    = (const float*)d_in[7];
    const float* lf2    = (const float*)d_in[8];
    const float* W1     = (const float*)d_in[9];
    const float* W2     = (const float*)d_in[10];
    const float* b1     = (const float*)d_in[11];
    const float* b2     = (const float*)d_in[12];
    const float* lnw    = (const float*)d_in[13];
    float* out          = (float*)d_out;

    static __half *pXT1, *pZ, *pW1, *pW2;
    static float *pC1, *pC2;
    static bool init_done = false;
    if (!init_done) {
        cudaGetSymbolAddress((void**)&pXT1, g_XT1);
        cudaGetSymbolAddress((void**)&pZ,   g_Z);
        cudaGetSymbolAddress((void**)&pW1,  g_W1t);
        cudaGetSymbolAddress((void**)&pW2,  g_W2p);
        cudaGetSymbolAddress((void**)&pC1,  g_C1);
        cudaGetSymbolAddress((void**)&pC2,  g_C2);
        cudaFuncSetAttribute(mma_gemm_kernel,
                             cudaFuncAttributeMaxDynamicSharedMemorySize, GSMEM_TOTAL);
        init_done = true;
    }

    // E0: XT1 (fp16)
    build_xt1_kernel<<<ROWS, 256>>>(inputs, lf1);

    // Weight transposes (single fp16)
    transpose_w1_kernel<<<dim3(DDIM / 32, DDIM / 32), dim3(32, 8)>>>(W1, DDIM, DDIM);
    transpose_w2p_kernel<<<dim3(N2P / 32, K2 / 32), dim3(32, 8)>>>(W2);

    // G1: C1 = XT1 @ W1   [16392,2048]x[2048,2048], single phase
    {
        dim3 grid(DDIM / 128, (ROWS + 127) / 128);   // 16 x 129
        mma_gemm_kernel<<<grid, 256, GSMEM_TOTAL>>>(pXT1, pW1, pC1, ROWS, DDIM, DDIM);
    }

    // E1: build Z from C1 (conv-2 shift folded into GEMM2 operand)
    build_z_kernel<<<TOK, 256>>>(lf2, b1);

    // G2: C2 = Z @ W2'   [16384,2048]x[2048,2048], single phase
    {
        dim3 grid(N2P / 128, TOK / 128);             // 16 x 128
        mma_gemm_kernel<<<grid, 256, GSMEM_TOTAL>>>(pZ, pW2, pC2, TOK, K2, N2P);
    }

    // E2: epilogue (bias + residual + RMSNorm), row-local now
    epilogue_kernel<<<TOK, 256>>>(inputs, b2, lnw, out);
}

// round 16
// speedup vs baseline: 3.7102x; 1.0150x over previous
#include <cuda_runtime.h>
#include <cuda_bf16.h>
#include <cuda_fp16.h>
#include <cstdint>
#include <cstddef>

// Problem constants (fixed by setup_inputs: BS=8, L=2048, D=2048, CACHE=64)
#define BSQ   8
#define LSEQ  2048
#define TOK   16384          // BS*L
#define ROWS  16392          // TOK + BS (padded buffer rows)
#define DDIM  2048
#define H1    1024           // conv1 output width
#define K2    2048           // GEMM2 K after Z-concat
#define N2P   2048           // GEMM2 N after fold

// ---------------------------------------------------------------------------
// Device-global scratch (allocation-free path)
// C1 stored fp16 (GEMM1 writes half directly): halves GEMM1-store + build_z
// read traffic; error model says +~1e-4 in quadrature, still 2.4x margin.
// ---------------------------------------------------------------------------
__device__ __half g_XT1[(size_t)ROWS * DDIM];
__device__ __half g_Z[(size_t)TOK * K2];         // Z = [XT2[p], XT2[p+1]]
__device__ __half g_W1t[(size_t)DDIM * DDIM];    // W1^T fp16 [N][K]
__device__ __half g_W2p[(size_t)N2P * K2];       // W2'^T fp16 [N][K]
__device__ __half g_C1[(size_t)ROWS * DDIM];     // fp16 conv1 GEMM output
__device__ float g_C2[(size_t)TOK * N2P];

// ---------------------------------------------------------------------------
// helpers
// ---------------------------------------------------------------------------
__device__ __forceinline__ uint32_t smem_u32(const void* p) {
    uint32_t a;
    asm("{ .reg .u64 t; cvta.to.shared.u64 t, %1; cvt.u32.u64 %0, t; }"
        : "=r"(a) : "l"(p));
    return a;
}
__device__ __forceinline__ void cp_async16(uint32_t dst, const void* src, uint32_t bytes) {
    asm volatile("cp.async.cg.shared.global [%0], [%1], 16, %2;"
                 :: "r"(dst), "l"(src), "r"(bytes) : "memory");
}
__device__ __forceinline__ void ldsm_x4(uint32_t& r0, uint32_t& r1,
                                        uint32_t& r2, uint32_t& r3, uint32_t addr) {
    asm volatile("ldmatrix.sync.aligned.m8n8.x4.shared.b16 {%0,%1,%2,%3}, [%4];"
                 : "=r"(r0), "=r"(r1), "=r"(r2), "=r"(r3) : "r"(addr));
}
__device__ __forceinline__ void mma_f16(float& c0, float& c1, float& c2, float& c3,
                                        uint32_t a0, uint32_t a1, uint32_t a2, uint32_t a3,
                                        uint32_t b0, uint32_t b1) {
    asm volatile(
        "mma.sync.aligned.m16n8k16.row.col.f32.f16.f16.f32 "
        "{%0,%1,%2,%3}, {%4,%5,%6,%7}, {%8,%9}, {%0,%1,%2,%3};"
        : "+f"(c0), "+f"(c1), "+f"(c2), "+f"(c3)
        : "r"(a0), "r"(a1), "r"(a2), "r"(a3), "r"(b0), "r"(b1));
}
__device__ __forceinline__ void mbar_wait(uint32_t mbar, uint32_t parity) {
    uint32_t done;
    asm volatile(
        "{\n\t.reg .pred p;\n\t"
        "mbarrier.try_wait.parity.acquire.cta.shared::cta.b64 p, [%1], %2;\n\t"
        "selp.b32 %0, 1, 0, p;\n\t}"
        : "=r"(done) : "r"(mbar), "r"(parity) : "memory");
    if (!done) {
        asm volatile(
            "{\n\t.reg .pred P1;\n\t"
            "WL_%=:\n\t"
            "mbarrier.try_wait.parity.acquire.cta.shared::cta.b64 P1, [%0], %1, 0x989680;\n\t"
            "@P1 bra.uni WD_%=;\n\t"
            "bra.uni WL_%=;\n\t"
            "WD_%=:\n\t}"
            :: "r"(mbar), "r"(parity) : "memory");
    }
}

// ---------------------------------------------------------------------------
// fp16 mma.sync GEMM: C[M,N] = A[M,K] * Bt[N,K]^T, single phase.
// Block tile 128x128x64, 8 warps (2x4), warp tile 64x32, 3-stage cp.async,
// DECOUPLED mbarrier pipeline (no block-wide barrier in the mainloop).
// Templated on output type: float (C2) or __half (C1).
// ---------------------------------------------------------------------------
#define GS 3
#define PITCH 144
#define ATILE_B (128 * PITCH)          // 18432
#define STAGE_B (2 * ATILE_B)          // 36864
#define GSMEM_TOTAL (GS * STAGE_B + 64)

template <typename OutT>
__global__ __launch_bounds__(256, 2)
void mma_gemm_kernel(const __half* __restrict__ A,
                     const __half* __restrict__ B,
                     OutT* __restrict__ C, int M, int K, int N)
{
    extern __shared__ char smem[];
    const uint32_t sbase = smem_u32(smem);
    const uint32_t mb    = sbase + GS * STAGE_B;   // full[3] @ +0, empty[3] @ +32
    const int tid  = threadIdx.x;
    const int wid  = tid >> 5;
    const int lane = tid & 31;
    const int wm   = wid & 1;          // 0..1
    const int wn   = wid >> 1;         // 0..3
    const int g    = lane >> 2;        // 0..7
    const int tig  = lane & 3;         // 0..3

    const int nbase = blockIdx.x * 128;
    const int mbase = blockIdx.y * 128;

    const int TOT = K >> 6;            // K tiles of 64

    if (tid == 0) {
        #pragma unroll
        for (int s = 0; s < GS; s++) {
            asm volatile("mbarrier.init.shared.b64 [%0], %1;"
                         :: "r"(mb + s * 8), "r"(256u) : "memory");
            asm volatile("mbarrier.init.shared.b64 [%0], %1;"
                         :: "r"(mb + 32 + s * 8), "r"(256u) : "memory");
        }
    }
    __syncthreads();

    // ldmatrix per-lane base offsets (within a stage's A / B region)
    const uint32_t aoff = (uint32_t)(wm * 64 + (lane & 7) + ((lane >> 3) & 1) * 8) * PITCH
                        + (uint32_t)(lane >> 4) * 16;
    const uint32_t boff = (uint32_t)(wn * 32 + ((lane >> 4) & 1) * 8 + (lane & 7)) * PITCH
                        + (uint32_t)((lane >> 3) & 1) * 16;

    // producer state: stage pst, round pk, K offset pkk
    int pst = 0, pk = 0;
    uint32_t pkk = 0;
    auto produce = [&]() {
        if (pk > 0) mbar_wait(mb + 32 + pst * 8, (uint32_t)((pk & 1) ^ 1));  // empty
        const uint32_t sA = sbase + pst * STAGE_B;
        const uint32_t sB = sA + ATILE_B;
        #pragma unroll
        for (int h = 0; h < 4; h++) {
            int c  = tid + h * 256;
            int r  = c >> 3;
            int cc = c & 7;
            int grow = mbase + r;
            uint32_t ok = (grow < M) ? 16u : 0u;
            const void* srcA = A + ((size_t)(ok ? grow : 0) * K + pkk + cc * 8);
            cp_async16(sA + r * PITCH + cc * 16, srcA, ok);
            const void* srcB = B + ((size_t)(nbase + r) * K + pkk + cc * 8);
            cp_async16(sB + r * PITCH + cc * 16, srcB, 16u);
        }
        asm volatile("cp.async.mbarrier.arrive.noinc.shared.b64 [%0];"
                     :: "r"(mb + pst * 8) : "memory");                        // full
        pkk += 64;
        if (++pst == GS) { pst = 0; pk++; }
    };

    float acc[4][4][4];
    #pragma unroll
    for (int mt = 0; mt < 4; mt++)
        #pragma unroll
        for (int nt = 0; nt < 4; nt++)
            #pragma unroll
            for (int e = 0; e < 4; e++)
                acc[mt][nt][e] = 0.f;

    // prologue: prefetch 2 stages
    produce(); produce();

    int cst = 0, ck = 0;
    for (int it = 0; it < TOT; it++) {
        mbar_wait(mb + cst * 8, (uint32_t)(ck & 1));    // full[cst], acquire

        const uint32_t sA = sbase + cst * STAGE_B;
        const uint32_t sB = sA + ATILE_B;

        auto do_chunk = [&](int kk) {
            uint32_t bf[4][2];
            #pragma unroll
            for (int np = 0; np < 2; np++) {
                ldsm_x4(bf[2 * np][0], bf[2 * np][1],
                        bf[2 * np + 1][0], bf[2 * np + 1][1],
                        sB + boff + (uint32_t)np * (16 * PITCH) + (uint32_t)kk * 2);
            }
            #pragma unroll
            for (int mt = 0; mt < 4; mt++) {
                uint32_t a0, a1, a2, a3;
                ldsm_x4(a0, a1, a2, a3,
                        sA + aoff + (uint32_t)mt * (16 * PITCH) + (uint32_t)kk * 2);
                #pragma unroll
                for (int nt = 0; nt < 4; nt++)
                    mma_f16(acc[mt][nt][0], acc[mt][nt][1],
                            acc[mt][nt][2], acc[mt][nt][3],
                            a0, a1, a2, a3, bf[nt][0], bf[nt][1]);
            }
        };

        do_chunk(0);
        if (it + 2 < TOT) produce();   // fills stage (it+2)%3, waits empty of it-1
        do_chunk(16);
        do_chunk(32);
        do_chunk(48);

        asm volatile("mbarrier.arrive.shared.b64 _, [%0];"
                     :: "r"(mb + 32 + cst * 8) : "memory");   // empty[cst], release
        if (++cst == GS) { cst = 0; ck++; }
    }

    // store (fp32 or fp16 depending on OutT)
    #pragma unroll
    for (int mt = 0; mt < 4; mt++) {
        int row = mbase + wm * 64 + mt * 16 + g;
        #pragma unroll
        for (int nt = 0; nt < 4; nt++) {
            int col = nbase + wn * 32 + nt * 8 + tig * 2;
            if (row < M) {
                if constexpr (sizeof(OutT) == 2) {
                    *(__half2*)((__half*)C + (size_t)row * N + col) =
                        __floats2half2_rn(acc[mt][nt][0], acc[mt][nt][1]);
                } else {
                    *(float2*)((float*)C + (size_t)row * N + col) =
                        make_float2(acc[mt][nt][0], acc[mt][nt][1]);
                }
            }
            if (row + 8 < M) {
                if constexpr (sizeof(OutT) == 2) {
                    *(__half2*)((__half*)C + (size_t)(row + 8) * N + col) =
                        __floats2half2_rn(acc[mt][nt][2], acc[mt][nt][3]);
                } else {
                    *(float2*)((float*)C + (size_t)(row + 8) * N + col) =
                        make_float2(acc[mt][nt][2], acc[mt][nt][3]);
                }
            }
        }
    }
}

// ---------------------------------------------------------------------------
// E0: build XT1 (fp16) from inputs/lf1 (p = s*2049+j; j==0 -> cache row)
// ---------------------------------------------------------------------------
__global__ void build_xt1_kernel(const float* __restrict__ inputs,
                                 const float* __restrict__ lf1)
{
    int p = blockIdx.x;
    int s = p / (LSEQ + 1);
    int j = p - s * (LSEQ + 1);
    const float* src = (j == 0)
        ? (lf1 + (size_t)s * DDIM)
        : (inputs + ((size_t)s * LSEQ + (j - 1)) * DDIM);
    __half* dh = g_XT1 + (size_t)p * DDIM;
    int base = threadIdx.x * 8;
    #pragma unroll
    for (int v = 0; v < 2; v++) {
        float4 x = *(const float4*)(src + base + v * 4);
        *(__half2*)(dh + base + v * 4)     = __floats2half2_rn(x.x, x.y);
        *(__half2*)(dh + base + v * 4 + 2) = __floats2half2_rn(x.z, x.w);
    }
}

// ---------------------------------------------------------------------------
// E1: build Z[t] = [ XT2[p] , XT2[p+1] ]  (p = s*2049 + j for token t=(s,j))
//   XT2[q] = (q at j==0) ? lf2[s] : C1[q-1,:1024] + C1[q,1024:] + b1
// C1 now fp16: half2 loads, float math, half2 stores.
// ---------------------------------------------------------------------------
__global__ void build_z_kernel(const float* __restrict__ lf2,
                               const float* __restrict__ b1)
{
    int t = blockIdx.x;
    int s = t >> 11;
    int j = t & 2047;
    size_t p = (size_t)s * (LSEQ + 1) + j;

    __half* z = g_Z + (size_t)t * K2;
    int base = threadIdx.x * 4;
    float4 bi = *(const float4*)(b1 + base);

    // half 1: XT2[p]
    float r1x, r1y, r1z, r1w;
    if (j == 0) {
        float4 r = *(const float4*)(lf2 + (size_t)s * H1 + base);
        r1x = r.x; r1y = r.y; r1z = r.z; r1w = r.w;
    } else {
        float2 a01 = __half22float2(*(const __half2*)(g_C1 + (p - 1) * DDIM + base));
        float2 a23 = __half22float2(*(const __half2*)(g_C1 + (p - 1) * DDIM + base + 2));
        float2 b01 = __half22float2(*(const __half2*)(g_C1 + p * DDIM + H1 + base));
        float2 b23 = __half22float2(*(const __half2*)(g_C1 + p * DDIM + H1 + base + 2));
        r1x = a01.x + b01.x + bi.x;  r1y = a01.y + b01.y + bi.y;
        r1z = a23.x + b23.x + bi.z;  r1w = a23.y + b23.y + bi.w;
    }
    // half 2: XT2[p+1] (always the conv path; p+1 has j>=1)
    float2 c01 = __half22float2(*(const __half2*)(g_C1 + p * DDIM + base));
    float2 c23 = __half22float2(*(const __half2*)(g_C1 + p * DDIM + base + 2));
    float2 d01 = __half22float2(*(const __half2*)(g_C1 + (p + 1) * DDIM + H1 + base));
    float2 d23 = __half22float2(*(const __half2*)(g_C1 + (p + 1) * DDIM + H1 + base + 2));
    float r2x = c01.x + d01.x + bi.x,  r2y = c01.y + d01.y + bi.y;
    float r2z = c23.x + d23.x + bi.z,  r2w = c23.y + d23.y + bi.w;

    *(__half2*)(z + base)          = __floats2half2_rn(r1x, r1y);
    *(__half2*)(z + base + 2)      = __floats2half2_rn(r1z, r1w);
    *(__half2*)(z + H1 + base)     = __floats2half2_rn(r2x, r2y);
    *(__half2*)(z + H1 + base + 2) = __floats2half2_rn(r2z, r2w);
}

// ---------------------------------------------------------------------------
// Transpose W1 -> fp16: g_W1t[c][r] = fp16(W[r][c]);  W is [R, Cc]
// ---------------------------------------------------------------------------
__global__ void transpose_w1_kernel(const float* __restrict__ W, int R, int Cc)
{
    __shared__ float t[32][33];
    int tx = threadIdx.x, ty = threadIdx.y;           // 32 x 8
    int r0 = blockIdx.y * 32, c0 = blockIdx.x * 32;
    #pragma unroll
    for (int k = 0; k < 4; k++)
        t[ty + 8 * k][tx] = W[(size_t)(r0 + ty + 8 * k) * Cc + c0 + tx];
    __syncthreads();
    #pragma unroll
    for (int k = 0; k < 4; k++) {
        int c = c0 + ty + 8 * k;
        int r = r0 + tx;
        g_W1t[(size_t)c * R + r] = __float2half_rn(t[tx][ty + 8 * k]);
    }
}

// ---------------------------------------------------------------------------
// Transpose W2' -> fp16: g_W2p[n][k'] (2048x2048), where
//   k' < 1024: W2[k'][n] ; k' >= 1024: W2[k'-1024][2048+n]   (W2 is [1024][4096])
// ---------------------------------------------------------------------------
__global__ void transpose_w2p_kernel(const float* __restrict__ W2)
{
    __shared__ float t[32][33];
    int tx = threadIdx.x, ty = threadIdx.y;           // 32 x 8
    int k0 = blockIdx.y * 32, n0 = blockIdx.x * 32;
    int half = k0 >> 10;
    int kr0  = k0 & 1023;
    #pragma unroll
    for (int u = 0; u < 4; u++)
        t[ty + 8 * u][tx] = W2[(size_t)(kr0 + ty + 8 * u) * 4096 + half * 2048 + n0 + tx];
    __syncthreads();
    #pragma unroll
    for (int u = 0; u < 4; u++) {
        int n = n0 + ty + 8 * u;
        int k = k0 + tx;
        g_W2p[(size_t)n * K2 + k] = __float2half_rn(t[tx][ty + 8 * u]);
    }
}

// ---------------------------------------------------------------------------
// E2: epilogue, row-local: out[t] = rmsnorm(C2[t] + b2 + inputs[t])
// ---------------------------------------------------------------------------
__global__ void epilogue_kernel(const float* __restrict__ inputs,
                                const float* __restrict__ b2,
                                const float* __restrict__ lnw,
                                float* __restrict__ out)
{
    int t = blockIdx.x;
    const float* rowA = g_C2 + (size_t)t * N2P;
    const float* xin  = inputs + (size_t)t * DDIM;

    int base = threadIdx.x * 8;
    float o[8];
    float ss = 0.f;
    #pragma unroll
    for (int v = 0; v < 2; v++) {
        float4 a  = *(const float4*)(rowA + base + v * 4);
        float4 bi = *(const float4*)(b2   + base + v * 4);
        float4 xi = *(const float4*)(xin  + base + v * 4);
        float r0 = a.x + bi.x + xi.x;
        float r1 = a.y + bi.y + xi.y;
        float r2 = a.z + bi.z + xi.z;
        float r3 = a.w + bi.w + xi.w;
        o[v * 4 + 0] = r0; o[v * 4 + 1] = r1; o[v * 4 + 2] = r2; o[v * 4 + 3] = r3;
        ss += r0 * r0 + r1 * r1 + r2 * r2 + r3 * r3;
    }

    __shared__ float red[8];
    #pragma unroll
    for (int off = 16; off > 0; off >>= 1)
        ss += __shfl_xor_sync(0xFFFFFFFFu, ss, off);
    int lane = threadIdx.x & 31;
    int wid  = threadIdx.x >> 5;
    if (lane == 0) red[wid] = ss;
    __syncthreads();
    float total = 0.f;
    #pragma unroll
    for (int w = 0; w < 8; w++) total += red[w];

    float scale = rsqrtf(total * (1.0f / DDIM) + 1e-6f);

    float* op = out + (size_t)t * DDIM;
    #pragma unroll
    for (int v = 0; v < 2; v++) {
        float4 lw = *(const float4*)(lnw + base + v * 4);
        float4 r;
        r.x = o[v * 4 + 0] * scale * lw.x;
        r.y = o[v * 4 + 1] * scale * lw.y;
        r.z = o[v * 4 + 2] * scale * lw.z;
        r.w = o[v * 4 + 3] * scale * lw.w;
        *(float4*)(op + base + v * 4) = r;
    }
}

// ---------------------------------------------------------------------------
// kernel_launch
// ---------------------------------------------------------------------------
extern "C" void kernel_launch(void* const* d_in, const int* in_sizes, int n_in,
                              void* d_out, int out_size)
{
    const float* inputs = (const float*)d_in[0];
    const float* lf1    = (const float*)d_in[7];
    const float* lf2    = (const float*)d_in[8];
    const float* W1     = (const float*)d_in[9];
    const float* W2     = (const float*)d_in[10];
    const float* b1     = (const float*)d_in[11];
    const float* b2     = (const float*)d_in[12];
    const float* lnw    = (const float*)d_in[13];
    float* out          = (float*)d_out;

    static __half *pXT1, *pZ, *pW1, *pW2, *pC1;
    static float *pC2;
    static bool init_done = false;
    if (!init_done) {
        cudaGetSymbolAddress((void**)&pXT1, g_XT1);
        cudaGetSymbolAddress((void**)&pZ,   g_Z);
        cudaGetSymbolAddress((void**)&pW1,  g_W1t);
        cudaGetSymbolAddress((void**)&pW2,  g_W2p);
        cudaGetSymbolAddress((void**)&pC1,  g_C1);
        cudaGetSymbolAddress((void**)&pC2,  g_C2);
        cudaFuncSetAttribute(mma_gemm_kernel<__half>,
                             cudaFuncAttributeMaxDynamicSharedMemorySize, GSMEM_TOTAL);
        cudaFuncSetAttribute(mma_gemm_kernel<float>,
                             cudaFuncAttributeMaxDynamicSharedMemorySize, GSMEM_TOTAL);
        init_done = true;
    }

    // E0: XT1 (fp16)
    build_xt1_kernel<<<ROWS, 256>>>(inputs, lf1);

    // Weight transposes (single fp16)
    transpose_w1_kernel<<<dim3(DDIM / 32, DDIM / 32), dim3(32, 8)>>>(W1, DDIM, DDIM);
    transpose_w2p_kernel<<<dim3(N2P / 32, K2 / 32), dim3(32, 8)>>>(W2);

    // G1: C1 = XT1 @ W1   [16392,2048]x[2048,2048], fp16 output
    {
        dim3 grid(DDIM / 128, (ROWS + 127) / 128);   // 16 x 129
        mma_gemm_kernel<__half><<<grid, 256, GSMEM_TOTAL>>>(pXT1, pW1, pC1,
                                                            ROWS, DDIM, DDIM);
    }

    // E1: build Z from C1 (conv-2 shift folded into GEMM2 operand)
    build_z_kernel<<<TOK, 256>>>(lf2, b1);

    // G2: C2 = Z @ W2'   [16384,2048]x[2048,2048], fp32 output
    {
        dim3 grid(N2P / 128, TOK / 128);             // 16 x 128
        mma_gemm_kernel<float><<<grid, 256, GSMEM_TOTAL>>>(pZ, pW2, pC2,
                                                           TOK, K2, N2P);
    }

    // E2: epilogue (bias + residual + RMSNorm), row-local
    epilogue_kernel<<<TOK, 256>>>(inputs, b2, lnw, out);
}